// round 14
// baseline (speedup 1.0000x reference)
#include <cuda_runtime.h>
#include <cuda_bf16.h>
#include <math.h>
#include <cstdint>

#define HH 128
#define CC 80
#define MAXN 24576
#define ASTRIDE 40                 // bf16 elems per smem row
#define TILE_B (128 * ASTRIDE * 2) // bytes per 128-row tile = 10240
#define TILE_E (128 * ASTRIDE)     // elems per 128-row tile = 5120
#define STAGE_B (4 * TILE_B)       // bf path stage = 40960 B
#define STAGE_E (4 * TILE_E)
#define A192_E (192 * ASTRIDE)     // k1 A tile elems = 7680
#define A192_B (A192_E * 2)        // 15360 bytes

// region sizes for fused converter (float4 quads)
#define N4_APW (128 * 1024 / 4)    // 32768
#define N4_FW  (128 * 224 / 4)     // 7168
#define N4_WIH ((size_t)CC * 768 * 128 / 4)

// ---------------- scratch ----------------------------------------------------
__device__ __align__(256) __nv_bfloat16 g_allf_h[(size_t)MAXN * 224];
__device__ __align__(256) __nv_bfloat16 g_allf_l[(size_t)MAXN * 224];
__device__ __align__(256) __nv_bfloat16 g_dec_h [(size_t)MAXN * 128];
__device__ __align__(256) __nv_bfloat16 g_dec_l [(size_t)MAXN * 128];
__device__ __align__(256) __nv_bfloat16 g_wih_h [(size_t)CC * 768 * 128];
__device__ __align__(256) __nv_bfloat16 g_wih_l [(size_t)CC * 768 * 128];
__device__ __align__(256) __nv_bfloat16 g_apw_h [128 * 1024];
__device__ __align__(256) __nv_bfloat16 g_apw_l [128 * 1024];
__device__ __align__(256) __nv_bfloat16 g_fw_h  [128 * 224];
__device__ __align__(256) __nv_bfloat16 g_fw_l  [128 * 224];
__device__ __align__(256) float g_xp  [(size_t)2 * MAXN * 384];
__device__ __align__(256) float g_hid [(size_t)2 * MAXN * 128];
__device__ int g_ucl[CC + 1];

// ---- fast packed bf16 conversion helpers ------------------------------------
__device__ __forceinline__ uint32_t pk_hi(float x, float y) {
    uint32_t r;
    asm("cvt.rn.bf16x2.f32 %0, %1, %2;" : "=r"(r) : "f"(y), "f"(x));
    return r;
}
__device__ __forceinline__ uint32_t pk_lo(float x, float y, uint32_t ph) {
    float hx = __uint_as_float(ph << 16);
    float hy = __uint_as_float(ph & 0xFFFF0000u);
    uint32_t r;
    float rx = x - hx, ry = y - hy;
    asm("cvt.rn.bf16x2.f32 %0, %1, %2;" : "=r"(r) : "f"(ry), "f"(rx));
    return r;
}

// ---- cp.async helpers --------------------------------------------------------
__device__ __forceinline__ void cp16(uint32_t dst, const void* src, bool pred) {
    int sz = pred ? 16 : 0;
    asm volatile("cp.async.cg.shared.global [%0], [%1], 16, %2;"
                 :: "r"(dst), "l"(src), "r"(sz));
}
#define CP_COMMIT() asm volatile("cp.async.commit_group;" ::: "memory")
#define CP_WAIT(n)  asm volatile("cp.async.wait_group %0;" :: "n"(n) : "memory")

// ---- K0': fused converter (apw | fw | wih) + ucl normalization --------------
__global__ __launch_bounds__(256) void kconv_all(
    const void* __restrict__ ucl_raw,
    const float* __restrict__ apw, const float* __restrict__ fw,
    const float* __restrict__ wih,
    __nv_bfloat16* __restrict__ apw_h, __nv_bfloat16* __restrict__ apw_l,
    __nv_bfloat16* __restrict__ fw_h,  __nv_bfloat16* __restrict__ fw_l,
    __nv_bfloat16* __restrict__ wih_h, __nv_bfloat16* __restrict__ wih_l)
{
    // block 0 additionally normalizes unique_class_len
    if (blockIdx.x == 0) {
        __shared__ int is64;
        const int* p32 = (const int*)ucl_raw;
        if (threadIdx.x == 0) is64 = (p32[1] == 0);
        __syncthreads();
        int i = threadIdx.x;
        if (i <= CC)
            g_ucl[i] = is64 ? (int)((const long long*)ucl_raw)[i] : p32[i];
    }
    size_t i = (size_t)blockIdx.x * blockDim.x + threadIdx.x;
    const float* src;
    __nv_bfloat16 *dh, *dl;
    size_t off;
    if (i < N4_APW)                { src = apw; dh = apw_h; dl = apw_l; off = i; }
    else if (i < N4_APW + N4_FW)   { src = fw;  dh = fw_h;  dl = fw_l;  off = i - N4_APW; }
    else if (i < N4_APW + N4_FW + N4_WIH)
                                   { src = wih; dh = wih_h; dl = wih_l; off = i - N4_APW - N4_FW; }
    else return;
    float4 v = reinterpret_cast<const float4*>(src)[off];
    uint32_t h0 = pk_hi(v.x, v.y), h1 = pk_hi(v.z, v.w);
    uint32_t l0 = pk_lo(v.x, v.y, h0), l1 = pk_lo(v.z, v.w, h1);
    reinterpret_cast<uint2*>(dh)[off] = make_uint2(h0, h1);
    reinterpret_cast<uint2*>(dl)[off] = make_uint2(l0, l1);
}

// ---- m16n8k16 bf16 MMA -------------------------------------------------------
__device__ __forceinline__ void mma16816(float c[4], const uint32_t a[4], const uint32_t b[2]) {
    asm volatile(
        "mma.sync.aligned.m16n8k16.row.col.f32.bf16.bf16.f32 "
        "{%0,%1,%2,%3}, {%4,%5,%6,%7}, {%8,%9}, {%0,%1,%2,%3};"
        : "+f"(c[0]), "+f"(c[1]), "+f"(c[2]), "+f"(c[3])
        : "r"(a[0]), "r"(a[1]), "r"(a[2]), "r"(a[3]), "r"(b[0]), "r"(b[1]));
}

// ---- shared MMA section (256 thr, warp tile 32x64) ---------------------------
__device__ __forceinline__ void mma_section(
    const __nv_bfloat16* Ah, const __nv_bfloat16* Al,
    const __nv_bfloat16* Wh, const __nv_bfloat16* Wl,
    int wm, int wn, int gid, int tig, float acc[2][8][4])
{
#pragma unroll
    for (int ks = 0; ks < 32; ks += 16) {
        uint32_t ah[2][4], al[2][4];
#pragma unroll
        for (int mf = 0; mf < 2; mf++) {
            int m0 = wm * 32 + mf * 16;
            int kc = ks + tig * 2;
            ah[mf][0] = *reinterpret_cast<const uint32_t*>(&Ah[(m0 + gid)     * ASTRIDE + kc]);
            ah[mf][1] = *reinterpret_cast<const uint32_t*>(&Ah[(m0 + gid + 8) * ASTRIDE + kc]);
            ah[mf][2] = *reinterpret_cast<const uint32_t*>(&Ah[(m0 + gid)     * ASTRIDE + kc + 8]);
            ah[mf][3] = *reinterpret_cast<const uint32_t*>(&Ah[(m0 + gid + 8) * ASTRIDE + kc + 8]);
            al[mf][0] = *reinterpret_cast<const uint32_t*>(&Al[(m0 + gid)     * ASTRIDE + kc]);
            al[mf][1] = *reinterpret_cast<const uint32_t*>(&Al[(m0 + gid + 8) * ASTRIDE + kc]);
            al[mf][2] = *reinterpret_cast<const uint32_t*>(&Al[(m0 + gid)     * ASTRIDE + kc + 8]);
            al[mf][3] = *reinterpret_cast<const uint32_t*>(&Al[(m0 + gid + 8) * ASTRIDE + kc + 8]);
        }
        uint32_t bh[8][2], bl[8][2];
#pragma unroll
        for (int nf = 0; nf < 8; nf++) {
            int n0 = wn * 64 + nf * 8;
            int kc = ks + tig * 2;
            bh[nf][0] = *reinterpret_cast<const uint32_t*>(&Wh[(n0 + gid) * ASTRIDE + kc]);
            bh[nf][1] = *reinterpret_cast<const uint32_t*>(&Wh[(n0 + gid) * ASTRIDE + kc + 8]);
            bl[nf][0] = *reinterpret_cast<const uint32_t*>(&Wl[(n0 + gid) * ASTRIDE + kc]);
            bl[nf][1] = *reinterpret_cast<const uint32_t*>(&Wl[(n0 + gid) * ASTRIDE + kc + 8]);
        }
#pragma unroll
        for (int mf = 0; mf < 2; mf++)
#pragma unroll
            for (int nf = 0; nf < 8; nf++) {
                mma16816(acc[mf][nf], ah[mf], bh[nf]);
                mma16816(acc[mf][nf], ah[mf], bl[nf]);
                mma16816(acc[mf][nf], al[mf], bh[nf]);
            }
    }
}

// ---- MMA section for k1: 3 m-frags x 8 n-frags (warp tile 48x64) -------------
__device__ __forceinline__ void mma_section3(
    const __nv_bfloat16* Ah, const __nv_bfloat16* Al,
    const __nv_bfloat16* Wh, const __nv_bfloat16* Wl,
    int wm, int wn, int gid, int tig, float acc[3][8][4])
{
#pragma unroll
    for (int ks = 0; ks < 32; ks += 16) {
        uint32_t ah[3][4], al[3][4];
#pragma unroll
        for (int mf = 0; mf < 3; mf++) {
            int m0 = wm * 48 + mf * 16;
            int kc = ks + tig * 2;
            ah[mf][0] = *reinterpret_cast<const uint32_t*>(&Ah[(m0 + gid)     * ASTRIDE + kc]);
            ah[mf][1] = *reinterpret_cast<const uint32_t*>(&Ah[(m0 + gid + 8) * ASTRIDE + kc]);
            ah[mf][2] = *reinterpret_cast<const uint32_t*>(&Ah[(m0 + gid)     * ASTRIDE + kc + 8]);
            ah[mf][3] = *reinterpret_cast<const uint32_t*>(&Ah[(m0 + gid + 8) * ASTRIDE + kc + 8]);
            al[mf][0] = *reinterpret_cast<const uint32_t*>(&Al[(m0 + gid)     * ASTRIDE + kc]);
            al[mf][1] = *reinterpret_cast<const uint32_t*>(&Al[(m0 + gid + 8) * ASTRIDE + kc]);
            al[mf][2] = *reinterpret_cast<const uint32_t*>(&Al[(m0 + gid)     * ASTRIDE + kc + 8]);
            al[mf][3] = *reinterpret_cast<const uint32_t*>(&Al[(m0 + gid + 8) * ASTRIDE + kc + 8]);
        }
#pragma unroll
        for (int nf = 0; nf < 8; nf++) {
            int n0 = wn * 64 + nf * 8;
            int kc = ks + tig * 2;
            uint32_t bh[2], bl[2];
            bh[0] = *reinterpret_cast<const uint32_t*>(&Wh[(n0 + gid) * ASTRIDE + kc]);
            bh[1] = *reinterpret_cast<const uint32_t*>(&Wh[(n0 + gid) * ASTRIDE + kc + 8]);
            bl[0] = *reinterpret_cast<const uint32_t*>(&Wl[(n0 + gid) * ASTRIDE + kc]);
            bl[1] = *reinterpret_cast<const uint32_t*>(&Wl[(n0 + gid) * ASTRIDE + kc + 8]);
#pragma unroll
            for (int mf = 0; mf < 3; mf++) {
                mma16816(acc[mf][nf], ah[mf], bh);
                mma16816(acc[mf][nf], ah[mf], bl);
                mma16816(acc[mf][nf], al[mf], bh);
            }
        }
    }
}

// ---- bf-path stage loader: 4 tiles via cp.async ------------------------------
__device__ __forceinline__ void ld_stage_bf(
    uint32_t sb, int tid,
    const __nv_bfloat16* __restrict__ Ah_g, const __nv_bfloat16* __restrict__ Al_g,
    int lda, int mValid,
    const __nv_bfloat16* __restrict__ Bh_g, const __nv_bfloat16* __restrict__ Bl_g,
    int ldb, int k0)
{
#pragma unroll
    for (int it = 0; it < 2; it++) {
        int idx = tid + it * 256;
        int r = idx >> 2, c8 = (idx & 3) * 8;
        uint32_t o = sb + (uint32_t)(r * ASTRIDE + c8) * 2;
        bool ok = (r < mValid);
        cp16(o,              Ah_g + (size_t)r * lda + k0 + c8, ok);
        cp16(o + TILE_B,     Al_g + (size_t)r * lda + k0 + c8, ok);
        cp16(o + 2 * TILE_B, Bh_g + (size_t)r * ldb + k0 + c8, true);
        cp16(o + 3 * TILE_B, Bl_g + (size_t)r * ldb + k0 + c8, true);
    }
    CP_COMMIT();
}

// ---- tile core (bf/bf, cp.async 2-stage) -------------------------------------
__device__ __forceinline__ void hmma_tile_bf(
    const __nv_bfloat16* __restrict__ Ah_g, const __nv_bfloat16* __restrict__ Al_g,
    int lda, int mValid,
    const __nv_bfloat16* __restrict__ Bh_g, const __nv_bfloat16* __restrict__ Bl_g,
    int ldb, int KTOT, char* dsm, float acc[2][8][4])
{
    const int tid  = threadIdx.x;
    const int w    = tid >> 5;
    const int lane = tid & 31;
    const int gid  = lane >> 2, tig = lane & 3;
    const int wm = w & 3, wn = w >> 2;

#pragma unroll
    for (int i = 0; i < 2; i++)
#pragma unroll
        for (int j = 0; j < 8; j++)
#pragma unroll
            for (int q = 0; q < 4; q++) acc[i][j][q] = 0.f;

    uint32_t sb0 = (uint32_t)__cvta_generic_to_shared(dsm);
    const __nv_bfloat16* se = reinterpret_cast<const __nv_bfloat16*>(dsm);

    ld_stage_bf(sb0, tid, Ah_g, Al_g, lda, mValid, Bh_g, Bl_g, ldb, 0);
    int p = 0;
    for (int k0 = 0; k0 < KTOT; k0 += 32) {
        bool hasNext = (k0 + 32 < KTOT);
        if (hasNext) {
            ld_stage_bf(sb0 + (uint32_t)(p ^ 1) * STAGE_B, tid,
                        Ah_g, Al_g, lda, mValid, Bh_g, Bl_g, ldb, k0 + 32);
            CP_WAIT(1);
        } else {
            CP_WAIT(0);
        }
        __syncthreads();
        const __nv_bfloat16* s = se + (size_t)p * STAGE_E;
        mma_section(s, s + TILE_E, s + 2 * TILE_E, s + 3 * TILE_E,
                    wm, wn, gid, tig, acc);
        __syncthreads();
        p ^= 1;
    }
}

// ---- K1 tile core: 192-row A (fp32 convert-on-stage), B cp.async 2-stage ----
__device__ __forceinline__ void hmma_tile_mixed192(
    const float* __restrict__ At, int lda, int mValid,
    const __nv_bfloat16* __restrict__ Bh_g, const __nv_bfloat16* __restrict__ Bl_g,
    int ldb, int KTOT, char* dsm, float acc[3][8][4])
{
    const int tid  = threadIdx.x;
    const int w    = tid >> 5;
    const int lane = tid & 31;
    const int gid  = lane >> 2, tig = lane & 3;
    const int wm = w & 3, wn = w >> 2;

#pragma unroll
    for (int i = 0; i < 3; i++)
#pragma unroll
        for (int j = 0; j < 8; j++)
#pragma unroll
            for (int q = 0; q < 4; q++) acc[i][j][q] = 0.f;

    __nv_bfloat16* Ah_s = reinterpret_cast<__nv_bfloat16*>(dsm);
    __nv_bfloat16* Al_s = Ah_s + A192_E;
    char* bBase = dsm + 2 * A192_B;
    uint32_t sbB = (uint32_t)__cvta_generic_to_shared(bBase);
    const __nv_bfloat16* bE = reinterpret_cast<const __nv_bfloat16*>(bBase);

    float4 pA[6];
#pragma unroll
    for (int it = 0; it < 6; it++) {
        int idx = tid + it * 256;
        int r = idx >> 3, c4 = (idx & 7) * 4;
        pA[it] = (r < mValid) ? *reinterpret_cast<const float4*>(At + (size_t)r * lda + c4)
                              : make_float4(0.f, 0.f, 0.f, 0.f);
    }
    {
#pragma unroll
        for (int it = 0; it < 2; it++) {
            int idx = tid + it * 256;
            int r = idx >> 2, c8 = (idx & 3) * 8;
            uint32_t o = sbB + (uint32_t)(r * ASTRIDE + c8) * 2;
            cp16(o,          Bh_g + (size_t)r * ldb + c8, true);
            cp16(o + TILE_B, Bl_g + (size_t)r * ldb + c8, true);
        }
        CP_COMMIT();
    }

    int p = 0;
    for (int k0 = 0; k0 < KTOT; k0 += 32) {
#pragma unroll
        for (int it = 0; it < 6; it++) {
            int idx = tid + it * 256;
            int r = idx >> 3, c4 = (idx & 7) * 4;
            int o = r * ASTRIDE + c4;
            float4 v = pA[it];
            uint32_t h0 = pk_hi(v.x, v.y), h1 = pk_hi(v.z, v.w);
            *reinterpret_cast<uint32_t*>(&Ah_s[o])     = h0;
            *reinterpret_cast<uint32_t*>(&Ah_s[o + 2]) = h1;
            *reinterpret_cast<uint32_t*>(&Al_s[o])     = pk_lo(v.x, v.y, h0);
            *reinterpret_cast<uint32_t*>(&Al_s[o + 2]) = pk_lo(v.z, v.w, h1);
        }
        bool hasNext = (k0 + 32 < KTOT);
        if (hasNext) {
#pragma unroll
            for (int it = 0; it < 2; it++) {
                int idx = tid + it * 256;
                int r = idx >> 2, c8 = (idx & 3) * 8;
                uint32_t o = sbB + (uint32_t)(p ^ 1) * (2 * TILE_B)
                           + (uint32_t)(r * ASTRIDE + c8) * 2;
                cp16(o,          Bh_g + (size_t)r * ldb + k0 + 32 + c8, true);
                cp16(o + TILE_B, Bl_g + (size_t)r * ldb + k0 + 32 + c8, true);
            }
            CP_COMMIT();
#pragma unroll
            for (int it = 0; it < 6; it++) {
                int idx = tid + it * 256;
                int r = idx >> 3, c4 = (idx & 7) * 4;
                pA[it] = (r < mValid) ? *reinterpret_cast<const float4*>(At + (size_t)r * lda + k0 + 32 + c4)
                                      : make_float4(0.f, 0.f, 0.f, 0.f);
            }
            CP_WAIT(1);
        } else {
            CP_WAIT(0);
        }
        __syncthreads();
        const __nv_bfloat16* bs = bE + (size_t)p * (2 * TILE_E);
        mma_section3(Ah_s, Al_s, bs, bs + TILE_E, wm, wn, gid, tig, acc);
        __syncthreads();
        p ^= 1;
    }
}

// ---- K1: feat = relu(A @ appear_W^T + b) -> allf (bf16 hi/lo); BM=192 -------
__global__ __launch_bounds__(256) void k1_appear(
    const float* __restrict__ feat_in,
    const float* __restrict__ score, const float* __restrict__ box,
    const float* __restrict__ origin,
    const float* __restrict__ b, int N)
{
    extern __shared__ char dsm[];
    const int tid  = threadIdx.x;
    const int w    = tid >> 5;
    const int lane = tid & 31;
    const int gid  = lane >> 2, tig = lane & 3;
    const int wm = w & 3, wn = w >> 2;
    const int mBase = blockIdx.x * 192;

    float acc[3][8][4];
    hmma_tile_mixed192(feat_in + (size_t)mBase * 1024, 1024, N - mBase,
                       g_apw_h, g_apw_l, 1024, 1024, dsm, acc);

#pragma unroll
    for (int mf = 0; mf < 3; mf++)
#pragma unroll
        for (int nf = 0; nf < 8; nf++) {
            int m0 = mBase + wm * 48 + mf * 16 + gid;
            int n0 = wn * 64 + nf * 8 + tig * 2;
            if (m0 < N) {
                float v0 = fmaxf(acc[mf][nf][0] + b[n0],     0.f);
                float v1 = fmaxf(acc[mf][nf][1] + b[n0 + 1], 0.f);
                uint32_t h = pk_hi(v0, v1);
                *reinterpret_cast<uint32_t*>(&g_allf_h[(size_t)m0 * 224 + n0]) = h;
                *reinterpret_cast<uint32_t*>(&g_allf_l[(size_t)m0 * 224 + n0]) = pk_lo(v0, v1, h);
            }
            if (m0 + 8 < N) {
                float v0 = fmaxf(acc[mf][nf][2] + b[n0],     0.f);
                float v1 = fmaxf(acc[mf][nf][3] + b[n0 + 1], 0.f);
                uint32_t h = pk_hi(v0, v1);
                *reinterpret_cast<uint32_t*>(&g_allf_h[(size_t)(m0 + 8) * 224 + n0]) = h;
                *reinterpret_cast<uint32_t*>(&g_allf_l[(size_t)(m0 + 8) * 224 + n0]) = pk_lo(v0, v1, h);
            }
        }
    for (int idx = tid; idx < 192 * 48; idx += 256) {
        int r = idx / 48, jp = idx % 48;
        int jc = jp * 2;
        int m = mBase + r;
        if (m < N) {
            float2 v;
            if (jc < 32)      v = *reinterpret_cast<const float2*>(score  + (size_t)m*32 + jc);
            else if (jc < 64) v = *reinterpret_cast<const float2*>(box    + (size_t)m*32 + jc - 32);
            else              v = *reinterpret_cast<const float2*>(origin + (size_t)m*32 + jc - 64);
            uint32_t h = pk_hi(v.x, v.y);
            *reinterpret_cast<uint32_t*>(&g_allf_h[(size_t)m * 224 + 128 + jc]) = h;
            *reinterpret_cast<uint32_t*>(&g_allf_l[(size_t)m * 224 + 128 + jc]) = pk_lo(v.x, v.y, h);
        }
    }
}

// ---- K2: dec = relu(allf @ feat_W^T + b) -> bf16 hi/lo, K=224 ---------------
__global__ __launch_bounds__(256, 2) void k2_dec(
    const float* __restrict__ b, int N)
{
    extern __shared__ char dsm[];
    const int tid  = threadIdx.x;
    const int w    = tid >> 5;
    const int lane = tid & 31;
    const int gid  = lane >> 2, tig = lane & 3;
    const int wm = w & 3, wn = w >> 2;
    const int mBase = blockIdx.x * 128;

    float acc[2][8][4];
    hmma_tile_bf(g_allf_h + (size_t)mBase * 224, g_allf_l + (size_t)mBase * 224, 224, N - mBase,
                 g_fw_h, g_fw_l, 224, 224, dsm, acc);

#pragma unroll
    for (int mf = 0; mf < 2; mf++)
#pragma unroll
        for (int nf = 0; nf < 8; nf++) {
            int m0 = mBase + wm * 32 + mf * 16 + gid;
            int n0 = wn * 64 + nf * 8 + tig * 2;
            if (m0 < N) {
                float v0 = fmaxf(acc[mf][nf][0] + b[n0],     0.f);
                float v1 = fmaxf(acc[mf][nf][1] + b[n0 + 1], 0.f);
                uint32_t h = pk_hi(v0, v1);
                *reinterpret_cast<uint32_t*>(&g_dec_h[(size_t)m0 * 128 + n0]) = h;
                *reinterpret_cast<uint32_t*>(&g_dec_l[(size_t)m0 * 128 + n0]) = pk_lo(v0, v1, h);
            }
            if (m0 + 8 < N) {
                float v0 = fmaxf(acc[mf][nf][2] + b[n0],     0.f);
                float v1 = fmaxf(acc[mf][nf][3] + b[n0 + 1], 0.f);
                uint32_t h = pk_hi(v0, v1);
                *reinterpret_cast<uint32_t*>(&g_dec_h[(size_t)(m0 + 8) * 128 + n0]) = h;
                *reinterpret_cast<uint32_t*>(&g_dec_l[(size_t)(m0 + 8) * 128 + n0]) = pk_lo(v0, v1, h);
            }
        }
}

// ---- K3: Xp = dec @ Wih^T + bih, both dirs, K=128 ---------------------------
__global__ __launch_bounds__(256, 2) void k3_xp(
    const float* __restrict__ bih, int N)
{
    int c = blockIdx.z;
    int start = g_ucl[c];
    int len = g_ucl[c+1] - start;
    int mBase = blockIdx.y * 128;
    if (mBase >= len) return;
    int nBase = blockIdx.x * 128;

    extern __shared__ char dsm[];
    const int tid  = threadIdx.x;
    const int w    = tid >> 5;
    const int lane = tid & 31;
    const int gid  = lane >> 2, tig = lane & 3;
    const int wm = w & 3, wn = w >> 2;

    float acc[2][8][4];
    size_t aoff = (size_t)(start + mBase) * 128;
    size_t boff = ((size_t)c * 768 + nBase) * 128;
    hmma_tile_bf(g_dec_h + aoff, g_dec_l + aoff, 128, len - mBase,
                 g_wih_h + boff, g_wih_l + boff, 128, 128, dsm, acc);

    const float* bb = bih + (size_t)c * 768;
    int d   = (nBase >= 384) ? 1 : 0;
    int nl0 = nBase - d * 384;
    float* dst = g_xp + (size_t)d * N * 384 + (size_t)start * 384;
#pragma unroll
    for (int mf = 0; mf < 2; mf++)
#pragma unroll
        for (int nf = 0; nf < 8; nf++) {
            int ml = mBase + wm * 32 + mf * 16 + gid;
            int n0 = wn * 64 + nf * 8 + tig * 2;
            int ng = nBase + n0;
            if (ml < len) {
                dst[(size_t)ml * 384 + nl0 + n0]     = acc[mf][nf][0] + bb[ng];
                dst[(size_t)ml * 384 + nl0 + n0 + 1] = acc[mf][nf][1] + bb[ng + 1];
            }
            if (ml + 8 < len) {
                dst[(size_t)(ml + 8) * 384 + nl0 + n0]     = acc[mf][nf][2] + bb[ng];
                dst[(size_t)(ml + 8) * 384 + nl0 + n0 + 1] = acc[mf][nf][3] + bb[ng + 1];
            }
        }
}

// ---- packed f32x2 FMA + fast tanh -------------------------------------------
__device__ __forceinline__ void fma2(unsigned long long& d,
                                     unsigned long long a,
                                     unsigned long long b) {
    asm("fma.rn.f32x2 %0, %1, %2, %0;" : "+l"(d) : "l"(a), "l"(b));
}
__device__ __forceinline__ float fast_tanh(float x) {
    float y;
    asm("tanh.approx.f32 %0, %1;" : "=f"(y) : "f"(x));
    return y;
}

// ---- K4: sequential GRU (R9 structure, unroll-bounded dot loop) --------------
__global__ __launch_bounds__(384, 1) void k4_gru(
    const float* __restrict__ Whh, const float* __restrict__ bhh, int N)
{
    int bid = blockIdx.x;
    int c = (CC - 1) - (bid >> 1);   // longest classes first
    int d = bid & 1;
    int start = g_ucl[c];
    int len = g_ucl[c+1] - start;
    int g = threadIdx.x;

    __shared__ __align__(16) float h_sm[128];
    __shared__ float pre[256];
    __shared__ float gh3[128];
    __shared__ float x3s[128];

    unsigned long long w2[64];
    {
        const ulonglong2* wp = reinterpret_cast<const ulonglong2*>(
            Whh + ((size_t)(c*2 + d) * 384 + g) * 128);
#pragma unroll
        for (int k = 0; k < 32; k++) {
            ulonglong2 v = wp[k];
            w2[2*k]   = v.x;
            w2[2*k+1] = v.y;
        }
    }
    float bg = bhh[(size_t)(c*2 + d) * 384 + g];
    if (g < 128) h_sm[g] = 0.f;
    __syncthreads();

    const float* Xp = g_xp  + (size_t)d * N * 384 + (size_t)start * 384;
    float* Hout     = g_hid + (size_t)d * N * 128 + (size_t)start * 128;

    int j  = (d == 0) ? 0 : len - 1;
    int dj = (d == 0) ? 1 : -1;
    float xg = (len > 0) ? Xp[(size_t)j * 384 + g] : 0.f;

    for (int step = 0; step < len; step++) {
        int jn = j + dj;
        float xn = 0.f;
        if (step + 1 < len) xn = Xp[(size_t)jn * 384 + g];

        unsigned long long a0 = 0ULL, a1 = 0ULL, a2 = 0ULL, a3 = 0ULL;
        const ulonglong2* h2p = reinterpret_cast<const ulonglong2*>(h_sm);
#pragma unroll 4
        for (int k = 0; k < 32; k += 2) {
            ulonglong2 hv0 = h2p[k];
            ulonglong2 hv1 = h2p[k+1];
            fma2(a0, w2[2*k],   hv0.x);
            fma2(a1, w2[2*k+1], hv0.y);
            fma2(a2, w2[2*k+2], hv1.x);
            fma2(a3, w2[2*k+3], hv1.y);
        }
        float2 f0 = *reinterpret_cast<float2*>(&a0);
        float2 f1 = *reinterpret_cast<float2*>(&a1);
        float2 f2 = *reinterpret_cast<float2*>(&a2);
        float2 f3 = *reinterpret_cast<float2*>(&a3);
        float gh = ((f0.x + f0.y) + (f1.x + f1.y))
                 + ((f2.x + f2.y) + (f3.x + f3.y)) + bg;

        if (g < 256) pre[g] = xg + gh;
        else { gh3[g - 256] = gh; x3s[g - 256] = xg; }
        __syncthreads();
        if (g < 128) {
            float r  = fmaf(fast_tanh(pre[g]       * 0.5f), 0.5f, 0.5f);
            float z  = fmaf(fast_tanh(pre[128 + g] * 0.5f), 0.5f, 0.5f);
            float u  = x3s[g] + r * gh3[g];
            float nn = fast_tanh(u);
            float hp = h_sm[g];
            float h2v = fmaf(z, hp - nn, nn);
            h_sm[g] = h2v;
            Hout[(size_t)j * 128 + g] = h2v;
        }
        __syncthreads();
        xg = xn;
        j = jn;
    }
}

// ---- K5: out = sigmoid([hf|hb] . out_W + b) --------------------------------
__global__ __launch_bounds__(256) void k5_out(
    const float* __restrict__ outW, const float* __restrict__ outb,
    float* __restrict__ out, int N)
{
    int t = blockIdx.x * blockDim.x + threadIdx.x;
    int row = t >> 5, lane = t & 31;
    if (row >= N) return;
    const float* hf = g_hid + (size_t)row * 128;
    const float* hb = g_hid + (size_t)N * 128 + (size_t)row * 128;
    float s = 0.f;
#pragma unroll
    for (int k = lane; k < 128; k += 32)
        s += outW[k] * hf[k] + outW[128 + k] * hb[k];
#pragma unroll
    for (int o = 16; o > 0; o >>= 1)
        s += __shfl_down_sync(0xffffffffu, s, o);
    if (lane == 0)
        out[row] = __fdividef(1.f, 1.f + __expf(-(s + outb[0])));
}

extern "C" void kernel_launch(void* const* d_in, const int* in_sizes, int n_in,
                              void* d_out, int out_size)
{
    const float* acb_feat  = (const float*)d_in[3];
    const float* acb_score = (const float*)d_in[4];
    const float* acb_box   = (const float*)d_in[5];
    const float* acb_orig  = (const float*)d_in[6];
    const void*  ucl_raw   = d_in[8];
    const float* appear_W  = (const float*)d_in[9];
    const float* appear_b  = (const float*)d_in[10];
    const float* feat_W    = (const float*)d_in[11];
    const float* feat_b    = (const float*)d_in[12];
    const float* gru_Wih   = (const float*)d_in[13];
    const float* gru_Whh   = (const float*)d_in[14];
    const float* gru_bih   = (const float*)d_in[15];
    const float* gru_bhh   = (const float*)d_in[16];
    const float* out_W     = (const float*)d_in[17];
    const float* out_b     = (const float*)d_in[18];

    int N = in_sizes[3] / 1024;
    if (N > MAXN) N = MAXN;
    int Mtiles1 = (N + 191) / 192;
    int Mtiles  = (N + 127) / 128;

    const int SMEM_K1 = 2 * A192_B + 4 * TILE_B;  // 71680
    const int SMEM_BF = 2 * STAGE_B;              // 81920
    cudaFuncSetAttribute(k1_appear, cudaFuncAttributeMaxDynamicSharedMemorySize, SMEM_K1);
    cudaFuncSetAttribute(k2_dec,    cudaFuncAttributeMaxDynamicSharedMemorySize, SMEM_BF);
    cudaFuncSetAttribute(k3_xp,     cudaFuncAttributeMaxDynamicSharedMemorySize, SMEM_BF);

    {
        __nv_bfloat16 *apw_h, *apw_l, *fw_h, *fw_l, *wih_h, *wih_l;
        cudaGetSymbolAddress((void**)&apw_h, g_apw_h);
        cudaGetSymbolAddress((void**)&apw_l, g_apw_l);
        cudaGetSymbolAddress((void**)&fw_h,  g_fw_h);
        cudaGetSymbolAddress((void**)&fw_l,  g_fw_l);
        cudaGetSymbolAddress((void**)&wih_h, g_wih_h);
        cudaGetSymbolAddress((void**)&wih_l, g_wih_l);
        size_t n4tot = N4_APW + N4_FW + N4_WIH;
        int blocks = (int)((n4tot + 255) / 256);
        kconv_all<<<blocks, 256>>>(ucl_raw, appear_W, feat_W, gru_Wih,
                                   apw_h, apw_l, fw_h, fw_l, wih_h, wih_l);
    }
    k1_appear<<<Mtiles1, 256, SMEM_K1>>>(acb_feat, acb_score, acb_box, acb_orig, appear_b, N);
    k2_dec<<<Mtiles, 256, SMEM_BF>>>(feat_b, N);
    dim3 g3(6, 4, CC);
    k3_xp<<<g3, 256, SMEM_BF>>>(gru_bih, N);   // launch index 3 -> ncu target
    k4_gru<<<2 * CC, 384>>>(gru_Whh, gru_bhh, N);
    k5_out<<<(N * 32 + 255) / 256, 256>>>(out_W, out_b, (float*)d_out, N);
}

// round 15
// speedup vs baseline: 1.9840x; 1.9840x over previous
#include <cuda_runtime.h>
#include <cuda_bf16.h>
#include <math.h>
#include <cstdint>

#define HH 128
#define CC 80
#define MAXN 24576
#define ASTRIDE 40                 // bf16 elems per smem row
#define TILE_B (128 * ASTRIDE * 2) // bytes per 128-row tile = 10240
#define TILE_E (128 * ASTRIDE)     // elems per 128-row tile = 5120
#define STAGE_B (4 * TILE_B)       // bf path stage = 40960 B
#define STAGE_E (4 * TILE_E)
#define A192_E (192 * ASTRIDE)     // k1 A tile elems = 7680
#define A192_B (A192_E * 2)        // 15360 bytes

// region sizes for fused converter (float4 quads)
#define N4_APW (128 * 1024 / 4)    // 32768
#define N4_FW  (128 * 224 / 4)     // 7168
#define N4_WIH ((size_t)CC * 768 * 128 / 4)

// ---------------- scratch ----------------------------------------------------
__device__ __align__(256) __nv_bfloat16 g_allf_h[(size_t)MAXN * 224];
__device__ __align__(256) __nv_bfloat16 g_allf_l[(size_t)MAXN * 224];
__device__ __align__(256) __nv_bfloat16 g_dec_h [(size_t)MAXN * 128];
__device__ __align__(256) __nv_bfloat16 g_dec_l [(size_t)MAXN * 128];
__device__ __align__(256) __nv_bfloat16 g_wih_h [(size_t)CC * 768 * 128];
__device__ __align__(256) __nv_bfloat16 g_wih_l [(size_t)CC * 768 * 128];
__device__ __align__(256) __nv_bfloat16 g_apw_h [128 * 1024];
__device__ __align__(256) __nv_bfloat16 g_apw_l [128 * 1024];
__device__ __align__(256) __nv_bfloat16 g_fw_h  [128 * 224];
__device__ __align__(256) __nv_bfloat16 g_fw_l  [128 * 224];
__device__ __align__(256) float g_xp  [(size_t)2 * MAXN * 384];
__device__ __align__(256) float g_hid [(size_t)2 * MAXN * 128];
__device__ int g_ucl[CC + 1];

// ---- fast packed bf16 conversion helpers ------------------------------------
__device__ __forceinline__ uint32_t pk_hi(float x, float y) {
    uint32_t r;
    asm("cvt.rn.bf16x2.f32 %0, %1, %2;" : "=r"(r) : "f"(y), "f"(x));
    return r;
}
__device__ __forceinline__ uint32_t pk_lo(float x, float y, uint32_t ph) {
    float hx = __uint_as_float(ph << 16);
    float hy = __uint_as_float(ph & 0xFFFF0000u);
    uint32_t r;
    float rx = x - hx, ry = y - hy;
    asm("cvt.rn.bf16x2.f32 %0, %1, %2;" : "=r"(r) : "f"(ry), "f"(rx));
    return r;
}

// ---- cp.async helpers --------------------------------------------------------
__device__ __forceinline__ void cp16(uint32_t dst, const void* src, bool pred) {
    int sz = pred ? 16 : 0;
    asm volatile("cp.async.cg.shared.global [%0], [%1], 16, %2;"
                 :: "r"(dst), "l"(src), "r"(sz));
}
#define CP_COMMIT() asm volatile("cp.async.commit_group;" ::: "memory")
#define CP_WAIT(n)  asm volatile("cp.async.wait_group %0;" :: "n"(n) : "memory")

// ---- K0': fused converter (apw | fw | wih) + ucl normalization --------------
__global__ __launch_bounds__(256) void kconv_all(
    const void* __restrict__ ucl_raw,
    const float* __restrict__ apw, const float* __restrict__ fw,
    const float* __restrict__ wih,
    __nv_bfloat16* __restrict__ apw_h, __nv_bfloat16* __restrict__ apw_l,
    __nv_bfloat16* __restrict__ fw_h,  __nv_bfloat16* __restrict__ fw_l,
    __nv_bfloat16* __restrict__ wih_h, __nv_bfloat16* __restrict__ wih_l)
{
    if (blockIdx.x == 0) {
        __shared__ int is64;
        const int* p32 = (const int*)ucl_raw;
        if (threadIdx.x == 0) is64 = (p32[1] == 0);
        __syncthreads();
        int i = threadIdx.x;
        if (i <= CC)
            g_ucl[i] = is64 ? (int)((const long long*)ucl_raw)[i] : p32[i];
    }
    size_t i = (size_t)blockIdx.x * blockDim.x + threadIdx.x;
    const float* src;
    __nv_bfloat16 *dh, *dl;
    size_t off;
    if (i < N4_APW)                { src = apw; dh = apw_h; dl = apw_l; off = i; }
    else if (i < N4_APW + N4_FW)   { src = fw;  dh = fw_h;  dl = fw_l;  off = i - N4_APW; }
    else if (i < N4_APW + N4_FW + N4_WIH)
                                   { src = wih; dh = wih_h; dl = wih_l; off = i - N4_APW - N4_FW; }
    else return;
    float4 v = reinterpret_cast<const float4*>(src)[off];
    uint32_t h0 = pk_hi(v.x, v.y), h1 = pk_hi(v.z, v.w);
    uint32_t l0 = pk_lo(v.x, v.y, h0), l1 = pk_lo(v.z, v.w, h1);
    reinterpret_cast<uint2*>(dh)[off] = make_uint2(h0, h1);
    reinterpret_cast<uint2*>(dl)[off] = make_uint2(l0, l1);
}

// ---- m16n8k16 bf16 MMA -------------------------------------------------------
__device__ __forceinline__ void mma16816(float c[4], const uint32_t a[4], const uint32_t b[2]) {
    asm volatile(
        "mma.sync.aligned.m16n8k16.row.col.f32.bf16.bf16.f32 "
        "{%0,%1,%2,%3}, {%4,%5,%6,%7}, {%8,%9}, {%0,%1,%2,%3};"
        : "+f"(c[0]), "+f"(c[1]), "+f"(c[2]), "+f"(c[3])
        : "r"(a[0]), "r"(a[1]), "r"(a[2]), "r"(a[3]), "r"(b[0]), "r"(b[1]));
}

// ---- shared MMA section (256 thr, warp tile 32x64) ---------------------------
__device__ __forceinline__ void mma_section(
    const __nv_bfloat16* Ah, const __nv_bfloat16* Al,
    const __nv_bfloat16* Wh, const __nv_bfloat16* Wl,
    int wm, int wn, int gid, int tig, float acc[2][8][4])
{
#pragma unroll
    for (int ks = 0; ks < 32; ks += 16) {
        uint32_t ah[2][4], al[2][4];
#pragma unroll
        for (int mf = 0; mf < 2; mf++) {
            int m0 = wm * 32 + mf * 16;
            int kc = ks + tig * 2;
            ah[mf][0] = *reinterpret_cast<const uint32_t*>(&Ah[(m0 + gid)     * ASTRIDE + kc]);
            ah[mf][1] = *reinterpret_cast<const uint32_t*>(&Ah[(m0 + gid + 8) * ASTRIDE + kc]);
            ah[mf][2] = *reinterpret_cast<const uint32_t*>(&Ah[(m0 + gid)     * ASTRIDE + kc + 8]);
            ah[mf][3] = *reinterpret_cast<const uint32_t*>(&Ah[(m0 + gid + 8) * ASTRIDE + kc + 8]);
            al[mf][0] = *reinterpret_cast<const uint32_t*>(&Al[(m0 + gid)     * ASTRIDE + kc]);
            al[mf][1] = *reinterpret_cast<const uint32_t*>(&Al[(m0 + gid + 8) * ASTRIDE + kc]);
            al[mf][2] = *reinterpret_cast<const uint32_t*>(&Al[(m0 + gid)     * ASTRIDE + kc + 8]);
            al[mf][3] = *reinterpret_cast<const uint32_t*>(&Al[(m0 + gid + 8) * ASTRIDE + kc + 8]);
        }
        uint32_t bh[8][2], bl[8][2];
#pragma unroll
        for (int nf = 0; nf < 8; nf++) {
            int n0 = wn * 64 + nf * 8;
            int kc = ks + tig * 2;
            bh[nf][0] = *reinterpret_cast<const uint32_t*>(&Wh[(n0 + gid) * ASTRIDE + kc]);
            bh[nf][1] = *reinterpret_cast<const uint32_t*>(&Wh[(n0 + gid) * ASTRIDE + kc + 8]);
            bl[nf][0] = *reinterpret_cast<const uint32_t*>(&Wl[(n0 + gid) * ASTRIDE + kc]);
            bl[nf][1] = *reinterpret_cast<const uint32_t*>(&Wl[(n0 + gid) * ASTRIDE + kc + 8]);
        }
#pragma unroll
        for (int mf = 0; mf < 2; mf++)
#pragma unroll
            for (int nf = 0; nf < 8; nf++) {
                mma16816(acc[mf][nf], ah[mf], bh[nf]);
                mma16816(acc[mf][nf], ah[mf], bl[nf]);
                mma16816(acc[mf][nf], al[mf], bh[nf]);
            }
    }
}

// ---- MMA section for k1: 3 m-frags x 8 n-frags (warp tile 48x64) -------------
__device__ __forceinline__ void mma_section3(
    const __nv_bfloat16* Ah, const __nv_bfloat16* Al,
    const __nv_bfloat16* Wh, const __nv_bfloat16* Wl,
    int wm, int wn, int gid, int tig, float acc[3][8][4])
{
#pragma unroll
    for (int ks = 0; ks < 32; ks += 16) {
        uint32_t ah[3][4], al[3][4];
#pragma unroll
        for (int mf = 0; mf < 3; mf++) {
            int m0 = wm * 48 + mf * 16;
            int kc = ks + tig * 2;
            ah[mf][0] = *reinterpret_cast<const uint32_t*>(&Ah[(m0 + gid)     * ASTRIDE + kc]);
            ah[mf][1] = *reinterpret_cast<const uint32_t*>(&Ah[(m0 + gid + 8) * ASTRIDE + kc]);
            ah[mf][2] = *reinterpret_cast<const uint32_t*>(&Ah[(m0 + gid)     * ASTRIDE + kc + 8]);
            ah[mf][3] = *reinterpret_cast<const uint32_t*>(&Ah[(m0 + gid + 8) * ASTRIDE + kc + 8]);
            al[mf][0] = *reinterpret_cast<const uint32_t*>(&Al[(m0 + gid)     * ASTRIDE + kc]);
            al[mf][1] = *reinterpret_cast<const uint32_t*>(&Al[(m0 + gid + 8) * ASTRIDE + kc]);
            al[mf][2] = *reinterpret_cast<const uint32_t*>(&Al[(m0 + gid)     * ASTRIDE + kc + 8]);
            al[mf][3] = *reinterpret_cast<const uint32_t*>(&Al[(m0 + gid + 8) * ASTRIDE + kc + 8]);
        }
#pragma unroll
        for (int nf = 0; nf < 8; nf++) {
            int n0 = wn * 64 + nf * 8;
            int kc = ks + tig * 2;
            uint32_t bh[2], bl[2];
            bh[0] = *reinterpret_cast<const uint32_t*>(&Wh[(n0 + gid) * ASTRIDE + kc]);
            bh[1] = *reinterpret_cast<const uint32_t*>(&Wh[(n0 + gid) * ASTRIDE + kc + 8]);
            bl[0] = *reinterpret_cast<const uint32_t*>(&Wl[(n0 + gid) * ASTRIDE + kc]);
            bl[1] = *reinterpret_cast<const uint32_t*>(&Wl[(n0 + gid) * ASTRIDE + kc + 8]);
#pragma unroll
            for (int mf = 0; mf < 3; mf++) {
                mma16816(acc[mf][nf], ah[mf], bh);
                mma16816(acc[mf][nf], ah[mf], bl);
                mma16816(acc[mf][nf], al[mf], bh);
            }
        }
    }
}

// ---- bf-path stage loader: 4 tiles via cp.async ------------------------------
__device__ __forceinline__ void ld_stage_bf(
    uint32_t sb, int tid,
    const __nv_bfloat16* __restrict__ Ah_g, const __nv_bfloat16* __restrict__ Al_g,
    int lda, int mValid,
    const __nv_bfloat16* __restrict__ Bh_g, const __nv_bfloat16* __restrict__ Bl_g,
    int ldb, int k0)
{
#pragma unroll
    for (int it = 0; it < 2; it++) {
        int idx = tid + it * 256;
        int r = idx >> 2, c8 = (idx & 3) * 8;
        uint32_t o = sb + (uint32_t)(r * ASTRIDE + c8) * 2;
        bool ok = (r < mValid);
        cp16(o,              Ah_g + (size_t)r * lda + k0 + c8, ok);
        cp16(o + TILE_B,     Al_g + (size_t)r * lda + k0 + c8, ok);
        cp16(o + 2 * TILE_B, Bh_g + (size_t)r * ldb + k0 + c8, true);
        cp16(o + 3 * TILE_B, Bl_g + (size_t)r * ldb + k0 + c8, true);
    }
    CP_COMMIT();
}

// ---- tile core (bf/bf, cp.async 2-stage) -------------------------------------
__device__ __forceinline__ void hmma_tile_bf(
    const __nv_bfloat16* __restrict__ Ah_g, const __nv_bfloat16* __restrict__ Al_g,
    int lda, int mValid,
    const __nv_bfloat16* __restrict__ Bh_g, const __nv_bfloat16* __restrict__ Bl_g,
    int ldb, int KTOT, char* dsm, float acc[2][8][4])
{
    const int tid  = threadIdx.x;
    const int w    = tid >> 5;
    const int lane = tid & 31;
    const int gid  = lane >> 2, tig = lane & 3;
    const int wm = w & 3, wn = w >> 2;

#pragma unroll
    for (int i = 0; i < 2; i++)
#pragma unroll
        for (int j = 0; j < 8; j++)
#pragma unroll
            for (int q = 0; q < 4; q++) acc[i][j][q] = 0.f;

    uint32_t sb0 = (uint32_t)__cvta_generic_to_shared(dsm);
    const __nv_bfloat16* se = reinterpret_cast<const __nv_bfloat16*>(dsm);

    ld_stage_bf(sb0, tid, Ah_g, Al_g, lda, mValid, Bh_g, Bl_g, ldb, 0);
    int p = 0;
    for (int k0 = 0; k0 < KTOT; k0 += 32) {
        bool hasNext = (k0 + 32 < KTOT);
        if (hasNext) {
            ld_stage_bf(sb0 + (uint32_t)(p ^ 1) * STAGE_B, tid,
                        Ah_g, Al_g, lda, mValid, Bh_g, Bl_g, ldb, k0 + 32);
            CP_WAIT(1);
        } else {
            CP_WAIT(0);
        }
        __syncthreads();
        const __nv_bfloat16* s = se + (size_t)p * STAGE_E;
        mma_section(s, s + TILE_E, s + 2 * TILE_E, s + 3 * TILE_E,
                    wm, wn, gid, tig, acc);
        __syncthreads();
        p ^= 1;
    }
}

// ---- K1 tile core: 192-row A (fp32 convert-on-stage), B cp.async 2-stage ----
__device__ __forceinline__ void hmma_tile_mixed192(
    const float* __restrict__ At, int lda, int mValid,
    const __nv_bfloat16* __restrict__ Bh_g, const __nv_bfloat16* __restrict__ Bl_g,
    int ldb, int KTOT, char* dsm, float acc[3][8][4])
{
    const int tid  = threadIdx.x;
    const int w    = tid >> 5;
    const int lane = tid & 31;
    const int gid  = lane >> 2, tig = lane & 3;
    const int wm = w & 3, wn = w >> 2;

#pragma unroll
    for (int i = 0; i < 3; i++)
#pragma unroll
        for (int j = 0; j < 8; j++)
#pragma unroll
            for (int q = 0; q < 4; q++) acc[i][j][q] = 0.f;

    __nv_bfloat16* Ah_s = reinterpret_cast<__nv_bfloat16*>(dsm);
    __nv_bfloat16* Al_s = Ah_s + A192_E;
    char* bBase = dsm + 2 * A192_B;
    uint32_t sbB = (uint32_t)__cvta_generic_to_shared(bBase);
    const __nv_bfloat16* bE = reinterpret_cast<const __nv_bfloat16*>(bBase);

    float4 pA[6];
#pragma unroll
    for (int it = 0; it < 6; it++) {
        int idx = tid + it * 256;
        int r = idx >> 3, c4 = (idx & 7) * 4;
        pA[it] = (r < mValid) ? *reinterpret_cast<const float4*>(At + (size_t)r * lda + c4)
                              : make_float4(0.f, 0.f, 0.f, 0.f);
    }
    {
#pragma unroll
        for (int it = 0; it < 2; it++) {
            int idx = tid + it * 256;
            int r = idx >> 2, c8 = (idx & 3) * 8;
            uint32_t o = sbB + (uint32_t)(r * ASTRIDE + c8) * 2;
            cp16(o,          Bh_g + (size_t)r * ldb + c8, true);
            cp16(o + TILE_B, Bl_g + (size_t)r * ldb + c8, true);
        }
        CP_COMMIT();
    }

    int p = 0;
    for (int k0 = 0; k0 < KTOT; k0 += 32) {
#pragma unroll
        for (int it = 0; it < 6; it++) {
            int idx = tid + it * 256;
            int r = idx >> 3, c4 = (idx & 7) * 4;
            int o = r * ASTRIDE + c4;
            float4 v = pA[it];
            uint32_t h0 = pk_hi(v.x, v.y), h1 = pk_hi(v.z, v.w);
            *reinterpret_cast<uint32_t*>(&Ah_s[o])     = h0;
            *reinterpret_cast<uint32_t*>(&Ah_s[o + 2]) = h1;
            *reinterpret_cast<uint32_t*>(&Al_s[o])     = pk_lo(v.x, v.y, h0);
            *reinterpret_cast<uint32_t*>(&Al_s[o + 2]) = pk_lo(v.z, v.w, h1);
        }
        bool hasNext = (k0 + 32 < KTOT);
        if (hasNext) {
#pragma unroll
            for (int it = 0; it < 2; it++) {
                int idx = tid + it * 256;
                int r = idx >> 2, c8 = (idx & 3) * 8;
                uint32_t o = sbB + (uint32_t)(p ^ 1) * (2 * TILE_B)
                           + (uint32_t)(r * ASTRIDE + c8) * 2;
                cp16(o,          Bh_g + (size_t)r * ldb + k0 + 32 + c8, true);
                cp16(o + TILE_B, Bl_g + (size_t)r * ldb + k0 + 32 + c8, true);
            }
            CP_COMMIT();
#pragma unroll
            for (int it = 0; it < 6; it++) {
                int idx = tid + it * 256;
                int r = idx >> 3, c4 = (idx & 7) * 4;
                pA[it] = (r < mValid) ? *reinterpret_cast<const float4*>(At + (size_t)r * lda + k0 + 32 + c4)
                                      : make_float4(0.f, 0.f, 0.f, 0.f);
            }
            CP_WAIT(1);
        } else {
            CP_WAIT(0);
        }
        __syncthreads();
        const __nv_bfloat16* bs = bE + (size_t)p * (2 * TILE_E);
        mma_section3(Ah_s, Al_s, bs, bs + TILE_E, wm, wn, gid, tig, acc);
        __syncthreads();
        p ^= 1;
    }
}

// ---- K1: feat = relu(A @ appear_W^T + b) -> allf (bf16 hi/lo); BM=192 -------
__global__ __launch_bounds__(256) void k1_appear(
    const float* __restrict__ feat_in,
    const float* __restrict__ score, const float* __restrict__ box,
    const float* __restrict__ origin,
    const float* __restrict__ b, int N)
{
    extern __shared__ char dsm[];
    const int tid  = threadIdx.x;
    const int w    = tid >> 5;
    const int lane = tid & 31;
    const int gid  = lane >> 2, tig = lane & 3;
    const int wm = w & 3, wn = w >> 2;
    const int mBase = blockIdx.x * 192;

    float acc[3][8][4];
    hmma_tile_mixed192(feat_in + (size_t)mBase * 1024, 1024, N - mBase,
                       g_apw_h, g_apw_l, 1024, 1024, dsm, acc);

#pragma unroll
    for (int mf = 0; mf < 3; mf++)
#pragma unroll
        for (int nf = 0; nf < 8; nf++) {
            int m0 = mBase + wm * 48 + mf * 16 + gid;
            int n0 = wn * 64 + nf * 8 + tig * 2;
            if (m0 < N) {
                float v0 = fmaxf(acc[mf][nf][0] + b[n0],     0.f);
                float v1 = fmaxf(acc[mf][nf][1] + b[n0 + 1], 0.f);
                uint32_t h = pk_hi(v0, v1);
                *reinterpret_cast<uint32_t*>(&g_allf_h[(size_t)m0 * 224 + n0]) = h;
                *reinterpret_cast<uint32_t*>(&g_allf_l[(size_t)m0 * 224 + n0]) = pk_lo(v0, v1, h);
            }
            if (m0 + 8 < N) {
                float v0 = fmaxf(acc[mf][nf][2] + b[n0],     0.f);
                float v1 = fmaxf(acc[mf][nf][3] + b[n0 + 1], 0.f);
                uint32_t h = pk_hi(v0, v1);
                *reinterpret_cast<uint32_t*>(&g_allf_h[(size_t)(m0 + 8) * 224 + n0]) = h;
                *reinterpret_cast<uint32_t*>(&g_allf_l[(size_t)(m0 + 8) * 224 + n0]) = pk_lo(v0, v1, h);
            }
        }
    for (int idx = tid; idx < 192 * 48; idx += 256) {
        int r = idx / 48, jp = idx % 48;
        int jc = jp * 2;
        int m = mBase + r;
        if (m < N) {
            float2 v;
            if (jc < 32)      v = *reinterpret_cast<const float2*>(score  + (size_t)m*32 + jc);
            else if (jc < 64) v = *reinterpret_cast<const float2*>(box    + (size_t)m*32 + jc - 32);
            else              v = *reinterpret_cast<const float2*>(origin + (size_t)m*32 + jc - 64);
            uint32_t h = pk_hi(v.x, v.y);
            *reinterpret_cast<uint32_t*>(&g_allf_h[(size_t)m * 224 + 128 + jc]) = h;
            *reinterpret_cast<uint32_t*>(&g_allf_l[(size_t)m * 224 + 128 + jc]) = pk_lo(v.x, v.y, h);
        }
    }
}

// ---- K2: dec = relu(allf @ feat_W^T + b) -> bf16 hi/lo, K=224 ---------------
__global__ __launch_bounds__(256, 2) void k2_dec(
    const float* __restrict__ b, int N)
{
    extern __shared__ char dsm[];
    const int tid  = threadIdx.x;
    const int w    = tid >> 5;
    const int lane = tid & 31;
    const int gid  = lane >> 2, tig = lane & 3;
    const int wm = w & 3, wn = w >> 2;
    const int mBase = blockIdx.x * 128;

    float acc[2][8][4];
    hmma_tile_bf(g_allf_h + (size_t)mBase * 224, g_allf_l + (size_t)mBase * 224, 224, N - mBase,
                 g_fw_h, g_fw_l, 224, 224, dsm, acc);

#pragma unroll
    for (int mf = 0; mf < 2; mf++)
#pragma unroll
        for (int nf = 0; nf < 8; nf++) {
            int m0 = mBase + wm * 32 + mf * 16 + gid;
            int n0 = wn * 64 + nf * 8 + tig * 2;
            if (m0 < N) {
                float v0 = fmaxf(acc[mf][nf][0] + b[n0],     0.f);
                float v1 = fmaxf(acc[mf][nf][1] + b[n0 + 1], 0.f);
                uint32_t h = pk_hi(v0, v1);
                *reinterpret_cast<uint32_t*>(&g_dec_h[(size_t)m0 * 128 + n0]) = h;
                *reinterpret_cast<uint32_t*>(&g_dec_l[(size_t)m0 * 128 + n0]) = pk_lo(v0, v1, h);
            }
            if (m0 + 8 < N) {
                float v0 = fmaxf(acc[mf][nf][2] + b[n0],     0.f);
                float v1 = fmaxf(acc[mf][nf][3] + b[n0 + 1], 0.f);
                uint32_t h = pk_hi(v0, v1);
                *reinterpret_cast<uint32_t*>(&g_dec_h[(size_t)(m0 + 8) * 128 + n0]) = h;
                *reinterpret_cast<uint32_t*>(&g_dec_l[(size_t)(m0 + 8) * 128 + n0]) = pk_lo(v0, v1, h);
            }
        }
}

// ---- K3: Xp = dec @ Wih^T + bih, both dirs, K=128 ---------------------------
__global__ __launch_bounds__(256, 2) void k3_xp(
    const float* __restrict__ bih, int N)
{
    int c = blockIdx.z;
    int start = g_ucl[c];
    int len = g_ucl[c+1] - start;
    int mBase = blockIdx.y * 128;
    if (mBase >= len) return;
    int nBase = blockIdx.x * 128;

    extern __shared__ char dsm[];
    const int tid  = threadIdx.x;
    const int w    = tid >> 5;
    const int lane = tid & 31;
    const int gid  = lane >> 2, tig = lane & 3;
    const int wm = w & 3, wn = w >> 2;

    float acc[2][8][4];
    size_t aoff = (size_t)(start + mBase) * 128;
    size_t boff = ((size_t)c * 768 + nBase) * 128;
    hmma_tile_bf(g_dec_h + aoff, g_dec_l + aoff, 128, len - mBase,
                 g_wih_h + boff, g_wih_l + boff, 128, 128, dsm, acc);

    const float* bb = bih + (size_t)c * 768;
    int d   = (nBase >= 384) ? 1 : 0;
    int nl0 = nBase - d * 384;
    float* dst = g_xp + (size_t)d * N * 384 + (size_t)start * 384;
#pragma unroll
    for (int mf = 0; mf < 2; mf++)
#pragma unroll
        for (int nf = 0; nf < 8; nf++) {
            int ml = mBase + wm * 32 + mf * 16 + gid;
            int n0 = wn * 64 + nf * 8 + tig * 2;
            int ng = nBase + n0;
            if (ml < len) {
                dst[(size_t)ml * 384 + nl0 + n0]     = acc[mf][nf][0] + bb[ng];
                dst[(size_t)ml * 384 + nl0 + n0 + 1] = acc[mf][nf][1] + bb[ng + 1];
            }
            if (ml + 8 < len) {
                dst[(size_t)(ml + 8) * 384 + nl0 + n0]     = acc[mf][nf][2] + bb[ng];
                dst[(size_t)(ml + 8) * 384 + nl0 + n0 + 1] = acc[mf][nf][3] + bb[ng + 1];
            }
        }
}

// ---- packed f32x2 FMA + fast tanh -------------------------------------------
__device__ __forceinline__ void fma2(unsigned long long& d,
                                     unsigned long long a,
                                     unsigned long long b) {
    asm("fma.rn.f32x2 %0, %1, %2, %0;" : "+l"(d) : "l"(a), "l"(b));
}
__device__ __forceinline__ float fast_tanh(float x) {
    float y;
    asm("tanh.approx.f32 %0, %1;" : "=f"(y) : "f"(x));
    return y;
}

// ---- K4: sequential GRU (R13-exact: FULL unroll, Whh in registers) ----------
__global__ __launch_bounds__(384, 1) void k4_gru(
    const float* __restrict__ Whh, const float* __restrict__ bhh, int N)
{
    int bid = blockIdx.x;
    int c = (CC - 1) - (bid >> 1);   // longest classes first
    int d = bid & 1;
    int start = g_ucl[c];
    int len = g_ucl[c+1] - start;
    int g = threadIdx.x;

    __shared__ __align__(16) float h_sm[128];
    __shared__ float pre[256];
    __shared__ float gh3[128];
    __shared__ float x3s[128];

    unsigned long long w2[64];
    {
        const ulonglong2* wp = reinterpret_cast<const ulonglong2*>(
            Whh + ((size_t)(c*2 + d) * 384 + g) * 128);
#pragma unroll
        for (int k = 0; k < 32; k++) {
            ulonglong2 v = wp[k];
            w2[2*k]   = v.x;
            w2[2*k+1] = v.y;
        }
    }
    float bg = bhh[(size_t)(c*2 + d) * 384 + g];
    if (g < 128) h_sm[g] = 0.f;
    __syncthreads();

    const float* Xp = g_xp  + (size_t)d * N * 384 + (size_t)start * 384;
    float* Hout     = g_hid + (size_t)d * N * 128 + (size_t)start * 128;

    int j  = (d == 0) ? 0 : len - 1;
    int dj = (d == 0) ? 1 : -1;
    float xg = (len > 0) ? Xp[(size_t)j * 384 + g] : 0.f;

    for (int step = 0; step < len; step++) {
        int jn = j + dj;
        float xn = 0.f;
        if (step + 1 < len) xn = Xp[(size_t)jn * 384 + g];

        unsigned long long a0 = 0ULL, a1 = 0ULL, a2 = 0ULL, a3 = 0ULL;
        const ulonglong2* h2p = reinterpret_cast<const ulonglong2*>(h_sm);
#pragma unroll
        for (int k = 0; k < 32; k += 2) {
            ulonglong2 hv0 = h2p[k];
            ulonglong2 hv1 = h2p[k+1];
            fma2(a0, w2[2*k],   hv0.x);
            fma2(a1, w2[2*k+1], hv0.y);
            fma2(a2, w2[2*k+2], hv1.x);
            fma2(a3, w2[2*k+3], hv1.y);
        }
        float2 f0 = *reinterpret_cast<float2*>(&a0);
        float2 f1 = *reinterpret_cast<float2*>(&a1);
        float2 f2 = *reinterpret_cast<float2*>(&a2);
        float2 f3 = *reinterpret_cast<float2*>(&a3);
        float gh = ((f0.x + f0.y) + (f1.x + f1.y))
                 + ((f2.x + f2.y) + (f3.x + f3.y)) + bg;

        if (g < 256) pre[g] = xg + gh;
        else { gh3[g - 256] = gh; x3s[g - 256] = xg; }
        __syncthreads();
        if (g < 128) {
            float r  = fmaf(fast_tanh(pre[g]       * 0.5f), 0.5f, 0.5f);
            float z  = fmaf(fast_tanh(pre[128 + g] * 0.5f), 0.5f, 0.5f);
            float u  = x3s[g] + r * gh3[g];
            float nn = fast_tanh(u);
            float hp = h_sm[g];
            float h2v = fmaf(z, hp - nn, nn);
            h_sm[g] = h2v;
            Hout[(size_t)j * 128 + g] = h2v;
        }
        __syncthreads();
        xg = xn;
        j = jn;
    }
}

// ---- K5: out = sigmoid([hf|hb] . out_W + b) --------------------------------
__global__ __launch_bounds__(256) void k5_out(
    const float* __restrict__ outW, const float* __restrict__ outb,
    float* __restrict__ out, int N)
{
    int t = blockIdx.x * blockDim.x + threadIdx.x;
    int row = t >> 5, lane = t & 31;
    if (row >= N) return;
    const float* hf = g_hid + (size_t)row * 128;
    const float* hb = g_hid + (size_t)N * 128 + (size_t)row * 128;
    float s = 0.f;
#pragma unroll
    for (int k = lane; k < 128; k += 32)
        s += outW[k] * hf[k] + outW[128 + k] * hb[k];
#pragma unroll
    for (int o = 16; o > 0; o >>= 1)
        s += __shfl_down_sync(0xffffffffu, s, o);
    if (lane == 0)
        out[row] = __fdividef(1.f, 1.f + __expf(-(s + outb[0])));
}

extern "C" void kernel_launch(void* const* d_in, const int* in_sizes, int n_in,
                              void* d_out, int out_size)
{
    const float* acb_feat  = (const float*)d_in[3];
    const float* acb_score = (const float*)d_in[4];
    const float* acb_box   = (const float*)d_in[5];
    const float* acb_orig  = (const float*)d_in[6];
    const void*  ucl_raw   = d_in[8];
    const float* appear_W  = (const float*)d_in[9];
    const float* appear_b  = (const float*)d_in[10];
    const float* feat_W    = (const float*)d_in[11];
    const float* feat_b    = (const float*)d_in[12];
    const float* gru_Wih   = (const float*)d_in[13];
    const float* gru_Whh   = (const float*)d_in[14];
    const float* gru_bih   = (const float*)d_in[15];
    const float* gru_bhh   = (const float*)d_in[16];
    const float* out_W     = (const float*)d_in[17];
    const float* out_b     = (const float*)d_in[18];

    int N = in_sizes[3] / 1024;
    if (N > MAXN) N = MAXN;
    int Mtiles1 = (N + 191) / 192;
    int Mtiles  = (N + 127) / 128;

    const int SMEM_K1 = 2 * A192_B + 4 * TILE_B;  // 71680
    const int SMEM_BF = 2 * STAGE_B;              // 81920
    cudaFuncSetAttribute(k1_appear, cudaFuncAttributeMaxDynamicSharedMemorySize, SMEM_K1);
    cudaFuncSetAttribute(k2_dec,    cudaFuncAttributeMaxDynamicSharedMemorySize, SMEM_BF);
    cudaFuncSetAttribute(k3_xp,     cudaFuncAttributeMaxDynamicSharedMemorySize, SMEM_BF);

    {
        __nv_bfloat16 *apw_h, *apw_l, *fw_h, *fw_l, *wih_h, *wih_l;
        cudaGetSymbolAddress((void**)&apw_h, g_apw_h);
        cudaGetSymbolAddress((void**)&apw_l, g_apw_l);
        cudaGetSymbolAddress((void**)&fw_h,  g_fw_h);
        cudaGetSymbolAddress((void**)&fw_l,  g_fw_l);
        cudaGetSymbolAddress((void**)&wih_h, g_wih_h);
        cudaGetSymbolAddress((void**)&wih_l, g_wih_l);
        size_t n4tot = N4_APW + N4_FW + N4_WIH;
        int blocks = (int)((n4tot + 255) / 256);
        kconv_all<<<blocks, 256>>>(ucl_raw, appear_W, feat_W, gru_Wih,
                                   apw_h, apw_l, fw_h, fw_l, wih_h, wih_l);
    }
    k1_appear<<<Mtiles1, 256, SMEM_K1>>>(acb_feat, acb_score, acb_box, acb_orig, appear_b, N);
    k2_dec<<<Mtiles, 256, SMEM_BF>>>(feat_b, N);
    dim3 g3(6, 4, CC);
    k3_xp<<<g3, 256, SMEM_BF>>>(gru_bih, N);   // launch index 3 -> ncu target
    k4_gru<<<2 * CC, 384>>>(gru_Whh, gru_bhh, N);
    k5_out<<<(N * 32 + 255) / 256, 256>>>(out_W, out_b, (float*)d_out, N);
}

// round 16
// speedup vs baseline: 2.0236x; 1.0199x over previous
#include <cuda_runtime.h>
#include <cuda_bf16.h>
#include <math.h>
#include <cstdint>

#define HH 128
#define CC 80
#define MAXN 24576
#define ASTRIDE 40                 // bf16 elems per smem row
#define TILE_B (128 * ASTRIDE * 2) // bytes per 128-row tile = 10240
#define TILE_E (128 * ASTRIDE)     // elems per 128-row tile = 5120
#define STAGE_B (4 * TILE_B)       // bf path stage = 40960 B
#define STAGE_E (4 * TILE_E)
#define A192_E (192 * ASTRIDE)     // 192-row A tile elems = 7680
#define A192_B (A192_E * 2)        // 15360 bytes

// region sizes for fused converter (float4 quads)
#define N4_APW (128 * 1024 / 4)    // 32768
#define N4_FW  (128 * 224 / 4)     // 7168
#define N4_WIH ((size_t)CC * 768 * 128 / 4)

// ---------------- scratch ----------------------------------------------------
__device__ __align__(256) __nv_bfloat16 g_allf_h[(size_t)MAXN * 224];
__device__ __align__(256) __nv_bfloat16 g_allf_l[(size_t)MAXN * 224];
__device__ __align__(256) __nv_bfloat16 g_dec_h [(size_t)MAXN * 128];
__device__ __align__(256) __nv_bfloat16 g_dec_l [(size_t)MAXN * 128];
__device__ __align__(256) __nv_bfloat16 g_wih_h [(size_t)CC * 768 * 128];
__device__ __align__(256) __nv_bfloat16 g_wih_l [(size_t)CC * 768 * 128];
__device__ __align__(256) __nv_bfloat16 g_apw_h [128 * 1024];
__device__ __align__(256) __nv_bfloat16 g_apw_l [128 * 1024];
__device__ __align__(256) __nv_bfloat16 g_fw_h  [128 * 224];
__device__ __align__(256) __nv_bfloat16 g_fw_l  [128 * 224];
__device__ __align__(256) float g_xp  [(size_t)2 * MAXN * 384];
__device__ __align__(256) float g_hid [(size_t)2 * MAXN * 128];
__device__ int g_ucl[CC + 1];

// ---- fast packed bf16 conversion helpers ------------------------------------
__device__ __forceinline__ uint32_t pk_hi(float x, float y) {
    uint32_t r;
    asm("cvt.rn.bf16x2.f32 %0, %1, %2;" : "=r"(r) : "f"(y), "f"(x));
    return r;
}
__device__ __forceinline__ uint32_t pk_lo(float x, float y, uint32_t ph) {
    float hx = __uint_as_float(ph << 16);
    float hy = __uint_as_float(ph & 0xFFFF0000u);
    uint32_t r;
    float rx = x - hx, ry = y - hy;
    asm("cvt.rn.bf16x2.f32 %0, %1, %2;" : "=r"(r) : "f"(ry), "f"(rx));
    return r;
}

// ---- cp.async helpers --------------------------------------------------------
__device__ __forceinline__ void cp16(uint32_t dst, const void* src, bool pred) {
    int sz = pred ? 16 : 0;
    asm volatile("cp.async.cg.shared.global [%0], [%1], 16, %2;"
                 :: "r"(dst), "l"(src), "r"(sz));
}
#define CP_COMMIT() asm volatile("cp.async.commit_group;" ::: "memory")
#define CP_WAIT(n)  asm volatile("cp.async.wait_group %0;" :: "n"(n) : "memory")

// ---- K0': fused converter (apw | fw | wih) + ucl normalization --------------
__global__ __launch_bounds__(256) void kconv_all(
    const void* __restrict__ ucl_raw,
    const float* __restrict__ apw, const float* __restrict__ fw,
    const float* __restrict__ wih,
    __nv_bfloat16* __restrict__ apw_h, __nv_bfloat16* __restrict__ apw_l,
    __nv_bfloat16* __restrict__ fw_h,  __nv_bfloat16* __restrict__ fw_l,
    __nv_bfloat16* __restrict__ wih_h, __nv_bfloat16* __restrict__ wih_l)
{
    if (blockIdx.x == 0) {
        __shared__ int is64;
        const int* p32 = (const int*)ucl_raw;
        if (threadIdx.x == 0) is64 = (p32[1] == 0);
        __syncthreads();
        int i = threadIdx.x;
        if (i <= CC)
            g_ucl[i] = is64 ? (int)((const long long*)ucl_raw)[i] : p32[i];
    }
    size_t i = (size_t)blockIdx.x * blockDim.x + threadIdx.x;
    const float* src;
    __nv_bfloat16 *dh, *dl;
    size_t off;
    if (i < N4_APW)                { src = apw; dh = apw_h; dl = apw_l; off = i; }
    else if (i < N4_APW + N4_FW)   { src = fw;  dh = fw_h;  dl = fw_l;  off = i - N4_APW; }
    else if (i < N4_APW + N4_FW + N4_WIH)
                                   { src = wih; dh = wih_h; dl = wih_l; off = i - N4_APW - N4_FW; }
    else return;
    float4 v = reinterpret_cast<const float4*>(src)[off];
    uint32_t h0 = pk_hi(v.x, v.y), h1 = pk_hi(v.z, v.w);
    uint32_t l0 = pk_lo(v.x, v.y, h0), l1 = pk_lo(v.z, v.w, h1);
    reinterpret_cast<uint2*>(dh)[off] = make_uint2(h0, h1);
    reinterpret_cast<uint2*>(dl)[off] = make_uint2(l0, l1);
}

// ---- m16n8k16 bf16 MMA -------------------------------------------------------
__device__ __forceinline__ void mma16816(float c[4], const uint32_t a[4], const uint32_t b[2]) {
    asm volatile(
        "mma.sync.aligned.m16n8k16.row.col.f32.bf16.bf16.f32 "
        "{%0,%1,%2,%3}, {%4,%5,%6,%7}, {%8,%9}, {%0,%1,%2,%3};"
        : "+f"(c[0]), "+f"(c[1]), "+f"(c[2]), "+f"(c[3])
        : "r"(a[0]), "r"(a[1]), "r"(a[2]), "r"(a[3]), "r"(b[0]), "r"(b[1]));
}

// ---- shared MMA section (256 thr, warp tile 32x64) ---------------------------
__device__ __forceinline__ void mma_section(
    const __nv_bfloat16* Ah, const __nv_bfloat16* Al,
    const __nv_bfloat16* Wh, const __nv_bfloat16* Wl,
    int wm, int wn, int gid, int tig, float acc[2][8][4])
{
#pragma unroll
    for (int ks = 0; ks < 32; ks += 16) {
        uint32_t ah[2][4], al[2][4];
#pragma unroll
        for (int mf = 0; mf < 2; mf++) {
            int m0 = wm * 32 + mf * 16;
            int kc = ks + tig * 2;
            ah[mf][0] = *reinterpret_cast<const uint32_t*>(&Ah[(m0 + gid)     * ASTRIDE + kc]);
            ah[mf][1] = *reinterpret_cast<const uint32_t*>(&Ah[(m0 + gid + 8) * ASTRIDE + kc]);
            ah[mf][2] = *reinterpret_cast<const uint32_t*>(&Ah[(m0 + gid)     * ASTRIDE + kc + 8]);
            ah[mf][3] = *reinterpret_cast<const uint32_t*>(&Ah[(m0 + gid + 8) * ASTRIDE + kc + 8]);
            al[mf][0] = *reinterpret_cast<const uint32_t*>(&Al[(m0 + gid)     * ASTRIDE + kc]);
            al[mf][1] = *reinterpret_cast<const uint32_t*>(&Al[(m0 + gid + 8) * ASTRIDE + kc]);
            al[mf][2] = *reinterpret_cast<const uint32_t*>(&Al[(m0 + gid)     * ASTRIDE + kc + 8]);
            al[mf][3] = *reinterpret_cast<const uint32_t*>(&Al[(m0 + gid + 8) * ASTRIDE + kc + 8]);
        }
        uint32_t bh[8][2], bl[8][2];
#pragma unroll
        for (int nf = 0; nf < 8; nf++) {
            int n0 = wn * 64 + nf * 8;
            int kc = ks + tig * 2;
            bh[nf][0] = *reinterpret_cast<const uint32_t*>(&Wh[(n0 + gid) * ASTRIDE + kc]);
            bh[nf][1] = *reinterpret_cast<const uint32_t*>(&Wh[(n0 + gid) * ASTRIDE + kc + 8]);
            bl[nf][0] = *reinterpret_cast<const uint32_t*>(&Wl[(n0 + gid) * ASTRIDE + kc]);
            bl[nf][1] = *reinterpret_cast<const uint32_t*>(&Wl[(n0 + gid) * ASTRIDE + kc + 8]);
        }
#pragma unroll
        for (int mf = 0; mf < 2; mf++)
#pragma unroll
            for (int nf = 0; nf < 8; nf++) {
                mma16816(acc[mf][nf], ah[mf], bh[nf]);
                mma16816(acc[mf][nf], ah[mf], bl[nf]);
                mma16816(acc[mf][nf], al[mf], bh[nf]);
            }
    }
}

// ---- MMA section: 3 m-frags x 8 n-frags (warp tile 48x64) --------------------
__device__ __forceinline__ void mma_section3(
    const __nv_bfloat16* Ah, const __nv_bfloat16* Al,
    const __nv_bfloat16* Wh, const __nv_bfloat16* Wl,
    int wm, int wn, int gid, int tig, float acc[3][8][4])
{
#pragma unroll
    for (int ks = 0; ks < 32; ks += 16) {
        uint32_t ah[3][4], al[3][4];
#pragma unroll
        for (int mf = 0; mf < 3; mf++) {
            int m0 = wm * 48 + mf * 16;
            int kc = ks + tig * 2;
            ah[mf][0] = *reinterpret_cast<const uint32_t*>(&Ah[(m0 + gid)     * ASTRIDE + kc]);
            ah[mf][1] = *reinterpret_cast<const uint32_t*>(&Ah[(m0 + gid + 8) * ASTRIDE + kc]);
            ah[mf][2] = *reinterpret_cast<const uint32_t*>(&Ah[(m0 + gid)     * ASTRIDE + kc + 8]);
            ah[mf][3] = *reinterpret_cast<const uint32_t*>(&Ah[(m0 + gid + 8) * ASTRIDE + kc + 8]);
            al[mf][0] = *reinterpret_cast<const uint32_t*>(&Al[(m0 + gid)     * ASTRIDE + kc]);
            al[mf][1] = *reinterpret_cast<const uint32_t*>(&Al[(m0 + gid + 8) * ASTRIDE + kc]);
            al[mf][2] = *reinterpret_cast<const uint32_t*>(&Al[(m0 + gid)     * ASTRIDE + kc + 8]);
            al[mf][3] = *reinterpret_cast<const uint32_t*>(&Al[(m0 + gid + 8) * ASTRIDE + kc + 8]);
        }
#pragma unroll
        for (int nf = 0; nf < 8; nf++) {
            int n0 = wn * 64 + nf * 8;
            int kc = ks + tig * 2;
            uint32_t bh[2], bl[2];
            bh[0] = *reinterpret_cast<const uint32_t*>(&Wh[(n0 + gid) * ASTRIDE + kc]);
            bh[1] = *reinterpret_cast<const uint32_t*>(&Wh[(n0 + gid) * ASTRIDE + kc + 8]);
            bl[0] = *reinterpret_cast<const uint32_t*>(&Wl[(n0 + gid) * ASTRIDE + kc]);
            bl[1] = *reinterpret_cast<const uint32_t*>(&Wl[(n0 + gid) * ASTRIDE + kc + 8]);
#pragma unroll
            for (int mf = 0; mf < 3; mf++) {
                mma16816(acc[mf][nf], ah[mf], bh);
                mma16816(acc[mf][nf], ah[mf], bl);
                mma16816(acc[mf][nf], al[mf], bh);
            }
        }
    }
}

// ---- bf-path stage loader: 4 tiles via cp.async (128-row A) ------------------
__device__ __forceinline__ void ld_stage_bf(
    uint32_t sb, int tid,
    const __nv_bfloat16* __restrict__ Ah_g, const __nv_bfloat16* __restrict__ Al_g,
    int lda, int mValid,
    const __nv_bfloat16* __restrict__ Bh_g, const __nv_bfloat16* __restrict__ Bl_g,
    int ldb, int k0)
{
#pragma unroll
    for (int it = 0; it < 2; it++) {
        int idx = tid + it * 256;
        int r = idx >> 2, c8 = (idx & 3) * 8;
        uint32_t o = sb + (uint32_t)(r * ASTRIDE + c8) * 2;
        bool ok = (r < mValid);
        cp16(o,              Ah_g + (size_t)r * lda + k0 + c8, ok);
        cp16(o + TILE_B,     Al_g + (size_t)r * lda + k0 + c8, ok);
        cp16(o + 2 * TILE_B, Bh_g + (size_t)r * ldb + k0 + c8, true);
        cp16(o + 3 * TILE_B, Bl_g + (size_t)r * ldb + k0 + c8, true);
    }
    CP_COMMIT();
}

// ---- tile core (bf/bf, cp.async 2-stage, 128-row A; used by k3) -------------
__device__ __forceinline__ void hmma_tile_bf(
    const __nv_bfloat16* __restrict__ Ah_g, const __nv_bfloat16* __restrict__ Al_g,
    int lda, int mValid,
    const __nv_bfloat16* __restrict__ Bh_g, const __nv_bfloat16* __restrict__ Bl_g,
    int ldb, int KTOT, char* dsm, float acc[2][8][4])
{
    const int tid  = threadIdx.x;
    const int w    = tid >> 5;
    const int lane = tid & 31;
    const int gid  = lane >> 2, tig = lane & 3;
    const int wm = w & 3, wn = w >> 2;

#pragma unroll
    for (int i = 0; i < 2; i++)
#pragma unroll
        for (int j = 0; j < 8; j++)
#pragma unroll
            for (int q = 0; q < 4; q++) acc[i][j][q] = 0.f;

    uint32_t sb0 = (uint32_t)__cvta_generic_to_shared(dsm);
    const __nv_bfloat16* se = reinterpret_cast<const __nv_bfloat16*>(dsm);

    ld_stage_bf(sb0, tid, Ah_g, Al_g, lda, mValid, Bh_g, Bl_g, ldb, 0);
    int p = 0;
    for (int k0 = 0; k0 < KTOT; k0 += 32) {
        bool hasNext = (k0 + 32 < KTOT);
        if (hasNext) {
            ld_stage_bf(sb0 + (uint32_t)(p ^ 1) * STAGE_B, tid,
                        Ah_g, Al_g, lda, mValid, Bh_g, Bl_g, ldb, k0 + 32);
            CP_WAIT(1);
        } else {
            CP_WAIT(0);
        }
        __syncthreads();
        const __nv_bfloat16* s = se + (size_t)p * STAGE_E;
        mma_section(s, s + TILE_E, s + 2 * TILE_E, s + 3 * TILE_E,
                    wm, wn, gid, tig, acc);
        __syncthreads();
        p ^= 1;
    }
}

// ---- tile core: 192-row A (fp32 convert-on-stage), B cp.async 2-stage -------
__device__ __forceinline__ void hmma_tile_mixed192(
    const float* __restrict__ At, int lda, int mValid,
    const __nv_bfloat16* __restrict__ Bh_g, const __nv_bfloat16* __restrict__ Bl_g,
    int ldb, int KTOT, char* dsm, float acc[3][8][4])
{
    const int tid  = threadIdx.x;
    const int w    = tid >> 5;
    const int lane = tid & 31;
    const int gid  = lane >> 2, tig = lane & 3;
    const int wm = w & 3, wn = w >> 2;

#pragma unroll
    for (int i = 0; i < 3; i++)
#pragma unroll
        for (int j = 0; j < 8; j++)
#pragma unroll
            for (int q = 0; q < 4; q++) acc[i][j][q] = 0.f;

    __nv_bfloat16* Ah_s = reinterpret_cast<__nv_bfloat16*>(dsm);
    __nv_bfloat16* Al_s = Ah_s + A192_E;
    char* bBase = dsm + 2 * A192_B;
    uint32_t sbB = (uint32_t)__cvta_generic_to_shared(bBase);
    const __nv_bfloat16* bE = reinterpret_cast<const __nv_bfloat16*>(bBase);

    float4 pA[6];
#pragma unroll
    for (int it = 0; it < 6; it++) {
        int idx = tid + it * 256;
        int r = idx >> 3, c4 = (idx & 7) * 4;
        pA[it] = (r < mValid) ? *reinterpret_cast<const float4*>(At + (size_t)r * lda + c4)
                              : make_float4(0.f, 0.f, 0.f, 0.f);
    }
    {
#pragma unroll
        for (int it = 0; it < 2; it++) {
            int idx = tid + it * 256;
            int r = idx >> 2, c8 = (idx & 3) * 8;
            uint32_t o = sbB + (uint32_t)(r * ASTRIDE + c8) * 2;
            cp16(o,          Bh_g + (size_t)r * ldb + c8, true);
            cp16(o + TILE_B, Bl_g + (size_t)r * ldb + c8, true);
        }
        CP_COMMIT();
    }

    int p = 0;
    for (int k0 = 0; k0 < KTOT; k0 += 32) {
#pragma unroll
        for (int it = 0; it < 6; it++) {
            int idx = tid + it * 256;
            int r = idx >> 3, c4 = (idx & 7) * 4;
            int o = r * ASTRIDE + c4;
            float4 v = pA[it];
            uint32_t h0 = pk_hi(v.x, v.y), h1 = pk_hi(v.z, v.w);
            *reinterpret_cast<uint32_t*>(&Ah_s[o])     = h0;
            *reinterpret_cast<uint32_t*>(&Ah_s[o + 2]) = h1;
            *reinterpret_cast<uint32_t*>(&Al_s[o])     = pk_lo(v.x, v.y, h0);
            *reinterpret_cast<uint32_t*>(&Al_s[o + 2]) = pk_lo(v.z, v.w, h1);
        }
        bool hasNext = (k0 + 32 < KTOT);
        if (hasNext) {
#pragma unroll
            for (int it = 0; it < 2; it++) {
                int idx = tid + it * 256;
                int r = idx >> 2, c8 = (idx & 3) * 8;
                uint32_t o = sbB + (uint32_t)(p ^ 1) * (2 * TILE_B)
                           + (uint32_t)(r * ASTRIDE + c8) * 2;
                cp16(o,          Bh_g + (size_t)r * ldb + k0 + 32 + c8, true);
                cp16(o + TILE_B, Bl_g + (size_t)r * ldb + k0 + 32 + c8, true);
            }
            CP_COMMIT();
#pragma unroll
            for (int it = 0; it < 6; it++) {
                int idx = tid + it * 256;
                int r = idx >> 3, c4 = (idx & 7) * 4;
                pA[it] = (r < mValid) ? *reinterpret_cast<const float4*>(At + (size_t)r * lda + k0 + 32 + c4)
                                      : make_float4(0.f, 0.f, 0.f, 0.f);
            }
            CP_WAIT(1);
        } else {
            CP_WAIT(0);
        }
        __syncthreads();
        const __nv_bfloat16* bs = bE + (size_t)p * (2 * TILE_E);
        mma_section3(Ah_s, Al_s, bs, bs + TILE_E, wm, wn, gid, tig, acc);
        __syncthreads();
        p ^= 1;
    }
}

// ---- tile core: 192-row A (bf16 hi/lo via LDG regs), B cp.async 2-stage -----
// A read with plain LDG (own-block store->load coherence after __syncthreads).
__device__ __forceinline__ void hmma_tile_bfreg192(
    const __nv_bfloat16* __restrict__ Ah_g, const __nv_bfloat16* __restrict__ Al_g,
    int lda, int mValid,
    const __nv_bfloat16* __restrict__ Bh_g, const __nv_bfloat16* __restrict__ Bl_g,
    int ldb, int KTOT, char* dsm, float acc[3][8][4])
{
    const int tid  = threadIdx.x;
    const int w    = tid >> 5;
    const int lane = tid & 31;
    const int gid  = lane >> 2, tig = lane & 3;
    const int wm = w & 3, wn = w >> 2;

#pragma unroll
    for (int i = 0; i < 3; i++)
#pragma unroll
        for (int j = 0; j < 8; j++)
#pragma unroll
            for (int q = 0; q < 4; q++) acc[i][j][q] = 0.f;

    __nv_bfloat16* Ah_s = reinterpret_cast<__nv_bfloat16*>(dsm);
    __nv_bfloat16* Al_s = Ah_s + A192_E;
    char* bBase = dsm + 2 * A192_B;
    uint32_t sbB = (uint32_t)__cvta_generic_to_shared(bBase);
    const __nv_bfloat16* bE = reinterpret_cast<const __nv_bfloat16*>(bBase);

    const uint4 z4 = make_uint4(0u, 0u, 0u, 0u);
    uint4 pAh[3], pAl[3];
#pragma unroll
    for (int it = 0; it < 3; it++) {
        int idx = tid + it * 256;
        int r = idx >> 2, c8 = (idx & 3) * 8;
        bool ok = (r < mValid);
        pAh[it] = ok ? *reinterpret_cast<const uint4*>(Ah_g + (size_t)r * lda + c8) : z4;
        pAl[it] = ok ? *reinterpret_cast<const uint4*>(Al_g + (size_t)r * lda + c8) : z4;
    }
    {
#pragma unroll
        for (int it = 0; it < 2; it++) {
            int idx = tid + it * 256;
            int r = idx >> 2, c8 = (idx & 3) * 8;
            uint32_t o = sbB + (uint32_t)(r * ASTRIDE + c8) * 2;
            cp16(o,          Bh_g + (size_t)r * ldb + c8, true);
            cp16(o + TILE_B, Bl_g + (size_t)r * ldb + c8, true);
        }
        CP_COMMIT();
    }

    int p = 0;
    for (int k0 = 0; k0 < KTOT; k0 += 32) {
#pragma unroll
        for (int it = 0; it < 3; it++) {
            int idx = tid + it * 256;
            int r = idx >> 2, c8 = (idx & 3) * 8;
            int o = r * ASTRIDE + c8;
            *reinterpret_cast<uint4*>(&Ah_s[o]) = pAh[it];
            *reinterpret_cast<uint4*>(&Al_s[o]) = pAl[it];
        }
        bool hasNext = (k0 + 32 < KTOT);
        if (hasNext) {
#pragma unroll
            for (int it = 0; it < 2; it++) {
                int idx = tid + it * 256;
                int r = idx >> 2, c8 = (idx & 3) * 8;
                uint32_t o = sbB + (uint32_t)(p ^ 1) * (2 * TILE_B)
                           + (uint32_t)(r * ASTRIDE + c8) * 2;
                cp16(o,          Bh_g + (size_t)r * ldb + k0 + 32 + c8, true);
                cp16(o + TILE_B, Bl_g + (size_t)r * ldb + k0 + 32 + c8, true);
            }
            CP_COMMIT();
#pragma unroll
            for (int it = 0; it < 3; it++) {
                int idx = tid + it * 256;
                int r = idx >> 2, c8 = (idx & 3) * 8;
                bool ok = (r < mValid);
                pAh[it] = ok ? *reinterpret_cast<const uint4*>(Ah_g + (size_t)r * lda + k0 + 32 + c8) : z4;
                pAl[it] = ok ? *reinterpret_cast<const uint4*>(Al_g + (size_t)r * lda + k0 + 32 + c8) : z4;
            }
            CP_WAIT(1);
        } else {
            CP_WAIT(0);
        }
        __syncthreads();
        const __nv_bfloat16* bs = bE + (size_t)p * (2 * TILE_E);
        mma_section3(Ah_s, Al_s, bs, bs + TILE_E, wm, wn, gid, tig, acc);
        __syncthreads();
        p ^= 1;
    }
}

// ---- K12: fused encoder: allf = [relu(A@apW^T+b) | extras];
//           dec = relu(allf @ fW^T + b2).  BM=192, block owns its rows. -------
__global__ __launch_bounds__(256) void k12_enc(
    const float* __restrict__ feat_in,
    const float* __restrict__ score, const float* __restrict__ box,
    const float* __restrict__ origin,
    const float* __restrict__ b1, const float* __restrict__ b2, int N)
{
    extern __shared__ char dsm[];
    const int tid  = threadIdx.x;
    const int w    = tid >> 5;
    const int lane = tid & 31;
    const int gid  = lane >> 2, tig = lane & 3;
    const int wm = w & 3, wn = w >> 2;
    const int mBase = blockIdx.x * 192;

    // ---- phase 1: appear GEMM (K=1024) ----
    {
        float acc[3][8][4];
        hmma_tile_mixed192(feat_in + (size_t)mBase * 1024, 1024, N - mBase,
                           g_apw_h, g_apw_l, 1024, 1024, dsm, acc);
#pragma unroll
        for (int mf = 0; mf < 3; mf++)
#pragma unroll
            for (int nf = 0; nf < 8; nf++) {
                int m0 = mBase + wm * 48 + mf * 16 + gid;
                int n0 = wn * 64 + nf * 8 + tig * 2;
                if (m0 < N) {
                    float v0 = fmaxf(acc[mf][nf][0] + b1[n0],     0.f);
                    float v1 = fmaxf(acc[mf][nf][1] + b1[n0 + 1], 0.f);
                    uint32_t h = pk_hi(v0, v1);
                    *reinterpret_cast<uint32_t*>(&g_allf_h[(size_t)m0 * 224 + n0]) = h;
                    *reinterpret_cast<uint32_t*>(&g_allf_l[(size_t)m0 * 224 + n0]) = pk_lo(v0, v1, h);
                }
                if (m0 + 8 < N) {
                    float v0 = fmaxf(acc[mf][nf][2] + b1[n0],     0.f);
                    float v1 = fmaxf(acc[mf][nf][3] + b1[n0 + 1], 0.f);
                    uint32_t h = pk_hi(v0, v1);
                    *reinterpret_cast<uint32_t*>(&g_allf_h[(size_t)(m0 + 8) * 224 + n0]) = h;
                    *reinterpret_cast<uint32_t*>(&g_allf_l[(size_t)(m0 + 8) * 224 + n0]) = pk_lo(v0, v1, h);
                }
            }
        for (int idx = tid; idx < 192 * 48; idx += 256) {
            int r = idx / 48, jp = idx % 48;
            int jc = jp * 2;
            int m = mBase + r;
            if (m < N) {
                float2 v;
                if (jc < 32)      v = *reinterpret_cast<const float2*>(score  + (size_t)m*32 + jc);
                else if (jc < 64) v = *reinterpret_cast<const float2*>(box    + (size_t)m*32 + jc - 32);
                else              v = *reinterpret_cast<const float2*>(origin + (size_t)m*32 + jc - 64);
                uint32_t h = pk_hi(v.x, v.y);
                *reinterpret_cast<uint32_t*>(&g_allf_h[(size_t)m * 224 + 128 + jc]) = h;
                *reinterpret_cast<uint32_t*>(&g_allf_l[(size_t)m * 224 + 128 + jc]) = pk_lo(v.x, v.y, h);
            }
        }
    }
    __syncthreads();   // allf rows of this block complete & visible block-wide

    // ---- phase 2: feat GEMM (K=224) over this block's own allf rows ----
    {
        float acc[3][8][4];
        hmma_tile_bfreg192(g_allf_h + (size_t)mBase * 224, g_allf_l + (size_t)mBase * 224,
                           224, N - mBase, g_fw_h, g_fw_l, 224, 224, dsm, acc);
#pragma unroll
        for (int mf = 0; mf < 3; mf++)
#pragma unroll
            for (int nf = 0; nf < 8; nf++) {
                int m0 = mBase + wm * 48 + mf * 16 + gid;
                int n0 = wn * 64 + nf * 8 + tig * 2;
                if (m0 < N) {
                    float v0 = fmaxf(acc[mf][nf][0] + b2[n0],     0.f);
                    float v1 = fmaxf(acc[mf][nf][1] + b2[n0 + 1], 0.f);
                    uint32_t h = pk_hi(v0, v1);
                    *reinterpret_cast<uint32_t*>(&g_dec_h[(size_t)m0 * 128 + n0]) = h;
                    *reinterpret_cast<uint32_t*>(&g_dec_l[(size_t)m0 * 128 + n0]) = pk_lo(v0, v1, h);
                }
                if (m0 + 8 < N) {
                    float v0 = fmaxf(acc[mf][nf][2] + b2[n0],     0.f);
                    float v1 = fmaxf(acc[mf][nf][3] + b2[n0 + 1], 0.f);
                    uint32_t h = pk_hi(v0, v1);
                    *reinterpret_cast<uint32_t*>(&g_dec_h[(size_t)(m0 + 8) * 128 + n0]) = h;
                    *reinterpret_cast<uint32_t*>(&g_dec_l[(size_t)(m0 + 8) * 128 + n0]) = pk_lo(v0, v1, h);
                }
            }
    }
}

// ---- K3: Xp = dec @ Wih^T + bih, both dirs, K=128 ---------------------------
__global__ __launch_bounds__(256, 2) void k3_xp(
    const float* __restrict__ bih, int N)
{
    int c = blockIdx.z;
    int start = g_ucl[c];
    int len = g_ucl[c+1] - start;
    int mBase = blockIdx.y * 128;
    if (mBase >= len) return;
    int nBase = blockIdx.x * 128;

    extern __shared__ char dsm[];
    const int tid  = threadIdx.x;
    const int w    = tid >> 5;
    const int lane = tid & 31;
    const int gid  = lane >> 2, tig = lane & 3;
    const int wm = w & 3, wn = w >> 2;

    float acc[2][8][4];
    size_t aoff = (size_t)(start + mBase) * 128;
    size_t boff = ((size_t)c * 768 + nBase) * 128;
    hmma_tile_bf(g_dec_h + aoff, g_dec_l + aoff, 128, len - mBase,
                 g_wih_h + boff, g_wih_l + boff, 128, 128, dsm, acc);

    const float* bb = bih + (size_t)c * 768;
    int d   = (nBase >= 384) ? 1 : 0;
    int nl0 = nBase - d * 384;
    float* dst = g_xp + (size_t)d * N * 384 + (size_t)start * 384;
#pragma unroll
    for (int mf = 0; mf < 2; mf++)
#pragma unroll
        for (int nf = 0; nf < 8; nf++) {
            int ml = mBase + wm * 32 + mf * 16 + gid;
            int n0 = wn * 64 + nf * 8 + tig * 2;
            int ng = nBase + n0;
            if (ml < len) {
                dst[(size_t)ml * 384 + nl0 + n0]     = acc[mf][nf][0] + bb[ng];
                dst[(size_t)ml * 384 + nl0 + n0 + 1] = acc[mf][nf][1] + bb[ng + 1];
            }
            if (ml + 8 < len) {
                dst[(size_t)(ml + 8) * 384 + nl0 + n0]     = acc[mf][nf][2] + bb[ng];
                dst[(size_t)(ml + 8) * 384 + nl0 + n0 + 1] = acc[mf][nf][3] + bb[ng + 1];
            }
        }
}

// ---- packed f32x2 FMA + fast tanh -------------------------------------------
__device__ __forceinline__ void fma2(unsigned long long& d,
                                     unsigned long long a,
                                     unsigned long long b) {
    asm("fma.rn.f32x2 %0, %1, %2, %0;" : "+l"(d) : "l"(a), "l"(b));
}
__device__ __forceinline__ float fast_tanh(float x) {
    float y;
    asm("tanh.approx.f32 %0, %1;" : "=f"(y) : "f"(x));
    return y;
}

// ---- K4: sequential GRU (R13-exact: FULL unroll, Whh in registers) ----------
__global__ __launch_bounds__(384, 1) void k4_gru(
    const float* __restrict__ Whh, const float* __restrict__ bhh, int N)
{
    int bid = blockIdx.x;
    int c = (CC - 1) - (bid >> 1);   // longest classes first
    int d = bid & 1;
    int start = g_ucl[c];
    int len = g_ucl[c+1] - start;
    int g = threadIdx.x;

    __shared__ __align__(16) float h_sm[128];
    __shared__ float pre[256];
    __shared__ float gh3[128];
    __shared__ float x3s[128];

    unsigned long long w2[64];
    {
        const ulonglong2* wp = reinterpret_cast<const ulonglong2*>(
            Whh + ((size_t)(c*2 + d) * 384 + g) * 128);
#pragma unroll
        for (int k = 0; k < 32; k++) {
            ulonglong2 v = wp[k];
            w2[2*k]   = v.x;
            w2[2*k+1] = v.y;
        }
    }
    float bg = bhh[(size_t)(c*2 + d) * 384 + g];
    if (g < 128) h_sm[g] = 0.f;
    __syncthreads();

    const float* Xp = g_xp  + (size_t)d * N * 384 + (size_t)start * 384;
    float* Hout     = g_hid + (size_t)d * N * 128 + (size_t)start * 128;

    int j  = (d == 0) ? 0 : len - 1;
    int dj = (d == 0) ? 1 : -1;
    float xg = (len > 0) ? Xp[(size_t)j * 384 + g] : 0.f;

    for (int step = 0; step < len; step++) {
        int jn = j + dj;
        float xn = 0.f;
        if (step + 1 < len) xn = Xp[(size_t)jn * 384 + g];

        unsigned long long a0 = 0ULL, a1 = 0ULL, a2 = 0ULL, a3 = 0ULL;
        const ulonglong2* h2p = reinterpret_cast<const ulonglong2*>(h_sm);
#pragma unroll
        for (int k = 0; k < 32; k += 2) {
            ulonglong2 hv0 = h2p[k];
            ulonglong2 hv1 = h2p[k+1];
            fma2(a0, w2[2*k],   hv0.x);
            fma2(a1, w2[2*k+1], hv0.y);
            fma2(a2, w2[2*k+2], hv1.x);
            fma2(a3, w2[2*k+3], hv1.y);
        }
        float2 f0 = *reinterpret_cast<float2*>(&a0);
        float2 f1 = *reinterpret_cast<float2*>(&a1);
        float2 f2 = *reinterpret_cast<float2*>(&a2);
        float2 f3 = *reinterpret_cast<float2*>(&a3);
        float gh = ((f0.x + f0.y) + (f1.x + f1.y))
                 + ((f2.x + f2.y) + (f3.x + f3.y)) + bg;

        if (g < 256) pre[g] = xg + gh;
        else { gh3[g - 256] = gh; x3s[g - 256] = xg; }
        __syncthreads();
        if (g < 128) {
            float r  = fmaf(fast_tanh(pre[g]       * 0.5f), 0.5f, 0.5f);
            float z  = fmaf(fast_tanh(pre[128 + g] * 0.5f), 0.5f, 0.5f);
            float u  = x3s[g] + r * gh3[g];
            float nn = fast_tanh(u);
            float hp = h_sm[g];
            float h2v = fmaf(z, hp - nn, nn);
            h_sm[g] = h2v;
            Hout[(size_t)j * 128 + g] = h2v;
        }
        __syncthreads();
        xg = xn;
        j = jn;
    }
}

// ---- K5: out = sigmoid([hf|hb] . out_W + b) --------------------------------
__global__ __launch_bounds__(256) void k5_out(
    const float* __restrict__ outW, const float* __restrict__ outb,
    float* __restrict__ out, int N)
{
    int t = blockIdx.x * blockDim.x + threadIdx.x;
    int row = t >> 5, lane = t & 31;
    if (row >= N) return;
    const float* hf = g_hid + (size_t)row * 128;
    const float* hb = g_hid + (size_t)N * 128 + (size_t)row * 128;
    float s = 0.f;
#pragma unroll
    for (int k = lane; k < 128; k += 32)
        s += outW[k] * hf[k] + outW[128 + k] * hb[k];
#pragma unroll
    for (int o = 16; o > 0; o >>= 1)
        s += __shfl_down_sync(0xffffffffu, s, o);
    if (lane == 0)
        out[row] = __fdividef(1.f, 1.f + __expf(-(s + outb[0])));
}

extern "C" void kernel_launch(void* const* d_in, const int* in_sizes, int n_in,
                              void* d_out, int out_size)
{
    const float* acb_feat  = (const float*)d_in[3];
    const float* acb_score = (const float*)d_in[4];
    const float* acb_box   = (const float*)d_in[5];
    const float* acb_orig  = (const float*)d_in[6];
    const void*  ucl_raw   = d_in[8];
    const float* appear_W  = (const float*)d_in[9];
    const float* appear_b  = (const float*)d_in[10];
    const float* feat_W    = (const float*)d_in[11];
    const float* feat_b    = (const float*)d_in[12];
    const float* gru_Wih   = (const float*)d_in[13];
    const float* gru_Whh   = (const float*)d_in[14];
    const float* gru_bih   = (const float*)d_in[15];
    const float* gru_bhh   = (const float*)d_in[16];
    const float* out_W     = (const float*)d_in[17];
    const float* out_b     = (const float*)d_in[18];

    int N = in_sizes[3] / 1024;
    if (N > MAXN) N = MAXN;
    int Mtiles1 = (N + 191) / 192;

    const int SMEM_K12 = 2 * A192_B + 4 * TILE_B;  // 71680 (both phases fit)
    const int SMEM_BF  = 2 * STAGE_B;              // 81920
    cudaFuncSetAttribute(k12_enc, cudaFuncAttributeMaxDynamicSharedMemorySize, SMEM_K12);
    cudaFuncSetAttribute(k3_xp,   cudaFuncAttributeMaxDynamicSharedMemorySize, SMEM_BF);

    {
        __nv_bfloat16 *apw_h, *apw_l, *fw_h, *fw_l, *wih_h, *wih_l;
        cudaGetSymbolAddress((void**)&apw_h, g_apw_h);
        cudaGetSymbolAddress((void**)&apw_l, g_apw_l);
        cudaGetSymbolAddress((void**)&fw_h,  g_fw_h);
        cudaGetSymbolAddress((void**)&fw_l,  g_fw_l);
        cudaGetSymbolAddress((void**)&wih_h, g_wih_h);
        cudaGetSymbolAddress((void**)&wih_l, g_wih_l);
        size_t n4tot = N4_APW + N4_FW + N4_WIH;
        int blocks = (int)((n4tot + 255) / 256);
        kconv_all<<<blocks, 256>>>(ucl_raw, appear_W, feat_W, gru_Wih,
                                   apw_h, apw_l, fw_h, fw_l, wih_h, wih_l);
    }
    k12_enc<<<Mtiles1, 256, SMEM_K12>>>(acb_feat, acb_score, acb_box, acb_orig,
                                        appear_b, feat_b, N);
    dim3 g3(6, 4, CC);
    k3_xp<<<g3, 256, SMEM_BF>>>(gru_bih, N);
    k4_gru<<<2 * CC, 384>>>(gru_Whh, gru_bhh, N);   // launch index 3 -> ncu target
    k5_out<<<(N * 32 + 255) / 256, 256>>>(out_W, out_b, (float*)d_out, N);
}